// round 12
// baseline (speedup 1.0000x reference)
#include <cuda_runtime.h>
#include <cuda_bf16.h>
#include <cuda_fp16.h>
#include <math.h>
#include <stdint.h>

#define NROWS 8192
#define NHALF 4096
#define DIN   512
#define DF    64      // feature dim padded (50 -> 64, zeros)
#define DOUT  50
#define HID   10
#define BM    128
#define BN    128
#define KC    64      // phase-1 k-chunk (bf16 elements; 128 B/row)
#define NB    (NROWS/BM)   // 64
#define NPAIR (NB*(NB+1)/2)  // 2080 upper-triangle tiles
#define NCHUNK (DIN/KC)    // 8
#define LDEH  130     // Et fp16 lead dim (halves)

// smem float offsets (same as R10/R11 layout)
#define OFF_A0  0
#define OFF_B0  4096
#define OFF_A1  8192
#define OFF_B1  12288
#define OFF_ET16 16384
#define SMEM_FLOATS (OFF_ET16 + (BM*LDEH)/2)   // 24704
#define SMEM_BYTES  (SMEM_FLOATS * 4)          // 98,816 B -> 2 CTAs/SM

// -------- scratch (no dynamic allocation allowed) --------
__device__ __nv_bfloat16 g_XcatH[NROWS*DIN];  // bf16-rounded concat(Xs,Xt)
__device__ float  g_FeaT[DF*NROWS];      // TRANSPOSED features [k][row], fp32
__device__ float  g_onorm[NROWS];        // norms of bf16-ROUNDED originals
__device__ float  g_fnorm[NROWS];
__device__ double g_acc[4];              // Sx, Sy, Smixed(2*sumKxy), Sdiag_xy
__device__ float  g_par[3];              // ep, 1/sigma, 1/sigma0

__device__ __forceinline__ float softplus_f(float x){
    return fmaxf(x, 0.f) + log1pf(expf(-fabsf(x)));
}

// exp(-x) for x >= 0, FMA-pipe only (no MUFU). ~3e-7 relative error.
__device__ __forceinline__ float exp_neg(float x){
    float t = x * -1.4426950408889634f;
    t = fmaxf(t, -125.f);
    float fn = t + 12582912.f;                   // 2^23 + 2^22 round magic
    int   ni = __float_as_int(fn) - 0x4B400000;
    float r  = t - (fn - 12582912.f);
    float p  = 1.5403530393e-4f;
    p = fmaf(p, r, 1.3333558146e-3f);
    p = fmaf(p, r, 9.6181291076e-3f);
    p = fmaf(p, r, 5.5504108665e-2f);
    p = fmaf(p, r, 2.4022650696e-1f);
    p = fmaf(p, r, 6.9314718056e-1f);
    p = fmaf(p, r, 1.0f);
    return __int_as_float(__float_as_int(p) + (ni << 23));
}

__device__ __forceinline__ void cp16(float* dst, const void* src){
    uint32_t d = (uint32_t)__cvta_generic_to_shared(dst);
    asm volatile("cp.async.cg.shared.global [%0], [%1], 16;\n"
                 :: "r"(d), "l"(src) : "memory");
}
__device__ __forceinline__ void cp_commit(){
    asm volatile("cp.async.commit_group;\n" ::: "memory");
}
__device__ __forceinline__ void ldsm4(uint32_t& r0, uint32_t& r1,
                                      uint32_t& r2, uint32_t& r3, uint32_t addr){
    asm volatile("ldmatrix.sync.aligned.m8n8.x4.shared.b16 {%0,%1,%2,%3}, [%4];"
                 : "=r"(r0), "=r"(r1), "=r"(r2), "=r"(r3) : "r"(addr));
}

// ---------------- init ----------------
__global__ void init_kernel(const float* __restrict__ eps,
                            const float* __restrict__ sig,
                            const float* __restrict__ sig0){
    if (threadIdx.x == 0){
        g_par[0] = 1.f / (1.f + expf(-eps[0]));
        g_par[1] = 1.f / (sig[0]  * sig[0]);
        g_par[2] = 1.f / (sig0[0] * sig0[0]);
        g_acc[0] = 0.0; g_acc[1] = 0.0; g_acc[2] = 0.0; g_acc[3] = 0.0;
    }
}

// ---------------- featurize: warp per row, 32 rows per block ----------------
__global__ __launch_bounds__(256)
void feat_kernel(const float* __restrict__ Xs, const float* __restrict__ Xt,
                 const float* __restrict__ W1, const float* __restrict__ b1,
                 const float* __restrict__ W2, const float* __restrict__ b2,
                 const float* __restrict__ W3, const float* __restrict__ b3,
                 const float* __restrict__ W4, const float* __restrict__ b4)
{
    __shared__ float sW1[DIN*HID];
    __shared__ float sW2[HID*HID], sW3[HID*HID], sW4[HID*DOUT];
    __shared__ float sb1[HID], sb2[HID], sb3[HID], sb4[DOUT];
    int tid = threadIdx.x;
    for (int i = tid; i < DIN*HID; i += 256) sW1[i] = W1[i];
    for (int i = tid; i < HID*HID; i += 256){ sW2[i] = W2[i]; sW3[i] = W3[i]; }
    for (int i = tid; i < HID*DOUT; i += 256) sW4[i] = W4[i];
    if (tid < HID){ sb1[tid] = b1[tid]; sb2[tid] = b2[tid]; sb3[tid] = b3[tid]; }
    if (tid < DOUT) sb4[tid] = b4[tid];
    __syncthreads();

    int warp = tid >> 5, lane = tid & 31;
    for (int pass = 0; pass < 4; pass++){
        int row = blockIdx.x * 32 + pass * 8 + warp;
        const float* src = (row < NHALF) ? (Xs + (size_t)row * DIN)
                                         : (Xt + (size_t)(row - NHALF) * DIN);
        float acc[HID];
        #pragma unroll
        for (int o = 0; o < HID; o++) acc[o] = 0.f;
        float on = 0.f;
        for (int k = lane; k < DIN; k += 32){
            float x = src[k];
            __nv_bfloat16 xb = __float2bfloat16_rn(x);  // round ONCE; Do exact-for-perturbed
            float xf = __bfloat162float(xb);
            g_XcatH[(size_t)row * DIN + k] = xb;
            on += xf * xf;
            #pragma unroll
            for (int o = 0; o < HID; o++) acc[o] += x * sW1[k*HID + o];
        }
        #pragma unroll
        for (int off = 16; off; off >>= 1){
            on += __shfl_xor_sync(0xffffffffu, on, off);
            #pragma unroll
            for (int o = 0; o < HID; o++)
                acc[o] += __shfl_xor_sync(0xffffffffu, acc[o], off);
        }
        if (lane == 0) g_onorm[row] = on;

        float h1[HID], h2[HID], h3[HID];
        #pragma unroll
        for (int o = 0; o < HID; o++) h1[o] = softplus_f(acc[o] + sb1[o]);
        #pragma unroll
        for (int o = 0; o < HID; o++){
            float t = sb2[o];
            #pragma unroll
            for (int p = 0; p < HID; p++) t += h1[p] * sW2[p*HID + o];
            h2[o] = softplus_f(t);
        }
        #pragma unroll
        for (int o = 0; o < HID; o++){
            float t = sb3[o];
            #pragma unroll
            for (int p = 0; p < HID; p++) t += h2[p] * sW3[p*HID + o];
            h3[o] = softplus_f(t);
        }
        float fn = 0.f;
        for (int c = lane; c < DF; c += 32){
            float v = 0.f;
            if (c < DOUT){
                v = sb4[c];
                #pragma unroll
                for (int p = 0; p < HID; p++) v += h3[p] * sW4[p*DOUT + c];
            }
            g_FeaT[(size_t)c * NROWS + row] = v;   // transposed for phase-2 cp.async
            fn += v * v;
        }
        #pragma unroll
        for (int off = 16; off; off >>= 1)
            fn += __shfl_xor_sync(0xffffffffu, fn, off);
        if (lane == 0) g_fnorm[row] = fn;
    }
}

// ---------------- fused pairwise kernel (packed triangular grid) ----------------
__global__ __launch_bounds__(256, 2)
void pair_kernel(){
    // decode linear block id -> (bi, bj), bj >= bi
    int t = blockIdx.x;
    float nf = (float)NB + 0.5f;
    int bi = (int)(nf - sqrtf(fmaxf(nf*nf - 2.0f*(float)t, 0.f)));
    bi = max(0, min(NB - 1, bi));
    while (bi > 0 && (bi*NB - bi*(bi-1)/2) > t) bi--;
    while (((bi+1)*NB - (bi+1)*bi/2) <= t) bi++;
    int bj = bi + (t - (bi*NB - bi*(bi-1)/2));

    extern __shared__ float smem[];
    const int tid  = threadIdx.x;
    const int lane = tid & 31, warp = tid >> 5;
    const int gid  = lane >> 2, tig = lane & 3;
    const int warpM = warp >> 1, warpN = warp & 1;   // 4 x 2 warp grid
    const int rw = warpM * 32;                 // warp row base (local)
    const int cw = warpN * 64;                 // warp col base (local)
    const int rowBase = bi * BM, colBase = bj * BN;

    // ldmatrix per-thread addressing constants
    const uint32_t smem_sh = (uint32_t)__cvta_generic_to_shared(smem);
    const int msel = lane >> 3, row8 = lane & 7;
    const int aGh = msel >> 1;                 // A: mats [m0-7 g0][m8-15 g0][m0-7 g1][m8-15 g1]
    const int bGh = msel & 1;                  // B: mats [n0 g0][n0 g1][n1 g0][n1 g1]
    uint32_t aRow[2], bRow[4];
    #pragma unroll
    for (int mi = 0; mi < 2; mi++)
        aRow[mi] = (uint32_t)(rw + mi*16 + (msel & 1)*8 + row8) * 128u;
    #pragma unroll
    for (int np = 0; np < 4; np++)
        bRow[np] = (uint32_t)(cw + (2*np + (msel >> 1))*8 + row8) * 128u;

    // ---- phase 1: original-space Gram via bf16 m16n8k16 (K = 512) ----
    float acc[2][8][4];
    #pragma unroll
    for (int mi = 0; mi < 2; mi++)
        #pragma unroll
        for (int ni = 0; ni < 8; ni++)
            #pragma unroll
            for (int r = 0; r < 4; r++) acc[mi][ni][r] = 0.f;

    #pragma unroll
    for (int st = 0; st < 2; st++){
        float* bA = smem + (st ? OFF_A1 : OFF_A0);
        float* bB = smem + (st ? OFF_B1 : OFF_B0);
        int kb = st * KC;
        #pragma unroll
        for (int i = 0; i < 4; i++){
            int idx = tid + i * 256;
            int r = idx >> 3, g = idx & 7;
            int sw = r*32 + (((g ^ (r & 7)) << 2));
            cp16(bA + sw, &g_XcatH[(size_t)(rowBase + r)*DIN + kb + (g << 3)]);
            cp16(bB + sw, &g_XcatH[(size_t)(colBase + r)*DIN + kb + (g << 3)]);
        }
        cp_commit();
    }

    for (int c = 0; c < NCHUNK; c++){
        if (c < NCHUNK - 1) asm volatile("cp.async.wait_group 1;\n" ::: "memory");
        else                asm volatile("cp.async.wait_group 0;\n" ::: "memory");
        __syncthreads();

        const uint32_t baseA = smem_sh + ((c & 1) ? OFF_A1 : OFF_A0) * 4u;
        const uint32_t baseB = smem_sh + ((c & 1) ? OFF_B1 : OFF_B0) * 4u;

        // B-fragment double buffer: prefetch B[ks+1] before HMMA(ks) so only
        // A's 2 LDSM sit on the critical path (regs: acc64 + A8 + B32 ~ fits 128)
        uint32_t a[2][4];
        uint32_t bfr[2][8][2];
        {   // B for ks=0
            #pragma unroll
            for (int np = 0; np < 4; np++){
                uint32_t ad = baseB + bRow[np] + ((uint32_t)((0 + bGh) ^ row8) << 4);
                ldsm4(bfr[0][2*np][0], bfr[0][2*np][1],
                      bfr[0][2*np+1][0], bfr[0][2*np+1][1], ad);
            }
        }
        #pragma unroll
        for (int ks = 0; ks < 4; ks++){
            const int cur = ks & 1, nxt = cur ^ 1;
            const int g0 = 2*ks;
            #pragma unroll
            for (int mi = 0; mi < 2; mi++){
                uint32_t ad = baseA + aRow[mi] + ((uint32_t)((g0 + aGh) ^ row8) << 4);
                ldsm4(a[mi][0], a[mi][1], a[mi][2], a[mi][3], ad);
            }
            if (ks < 3){
                const int g1 = 2*(ks+1);
                #pragma unroll
                for (int np = 0; np < 4; np++){
                    uint32_t ad = baseB + bRow[np] + ((uint32_t)((g1 + bGh) ^ row8) << 4);
                    ldsm4(bfr[nxt][2*np][0], bfr[nxt][2*np][1],
                          bfr[nxt][2*np+1][0], bfr[nxt][2*np+1][1], ad);
                }
            }
            #pragma unroll
            for (int mi = 0; mi < 2; mi++)
                #pragma unroll
                for (int ni = 0; ni < 8; ni++){
                    asm volatile(
                        "mma.sync.aligned.m16n8k16.row.col.f32.bf16.bf16.f32 "
                        "{%0,%1,%2,%3}, {%4,%5,%6,%7}, {%8,%9}, {%0,%1,%2,%3};\n"
                        : "+f"(acc[mi][ni][0]), "+f"(acc[mi][ni][1]),
                          "+f"(acc[mi][ni][2]), "+f"(acc[mi][ni][3])
                        : "r"(a[mi][0]), "r"(a[mi][1]), "r"(a[mi][2]), "r"(a[mi][3]),
                          "r"(bfr[cur][ni][0]), "r"(bfr[cur][ni][1]));
                }
        }
        __syncthreads();     // all warps done reading buf[c&1] before refill

        if (c + 2 < NCHUNK){
            float* bA = smem + ((c & 1) ? OFF_A1 : OFF_A0);
            float* bB = smem + ((c & 1) ? OFF_B1 : OFF_B0);
            int kb = (c + 2) * KC;
            #pragma unroll
            for (int i = 0; i < 4; i++){
                int idx = tid + i * 256;
                int r = idx >> 3, g = idx & 7;
                int sw = r*32 + (((g ^ (r & 7)) << 2));
                cp16(bA + sw, &g_XcatH[(size_t)(rowBase + r)*DIN + kb + (g << 3)]);
                cp16(bB + sw, &g_XcatH[(size_t)(colBase + r)*DIN + kb + (g << 3)]);
            }
            cp_commit();
        }
    }
    // All phase-1 buffers dead now.

    // Prefetch BOTH transposed Fea tiles into [0,16384) floats (overlaps Et epilogue).
    #pragma unroll
    for (int i = 0; i < 8; i++){
        int idx = tid + i * 256;
        int k = idx >> 5, gr = (idx & 31) << 2;
        cp16(smem + k*128 + gr,        &g_FeaT[(size_t)k*NROWS + rowBase + gr]);
        cp16(smem + 8192 + k*128 + gr, &g_FeaT[(size_t)k*NROWS + colBase + gr]);
    }
    cp_commit();

    const float ep    = g_par[0];
    const float invs  = g_par[1];
    const float invs0 = g_par[2];
    __half* Et16 = (__half*)(smem + OFF_ET16); // [128][LDEH] halves

    {   // phase-1 epilogue: Do -> e_org, stage into Et16 (fragment -> (row,col))
        float rn[4], cn[16];
        #pragma unroll
        for (int mi = 0; mi < 2; mi++)
            #pragma unroll
            for (int rr = 0; rr < 2; rr++)
                rn[mi*2+rr] = g_onorm[rowBase + rw + mi*16 + rr*8 + gid];
        #pragma unroll
        for (int ni = 0; ni < 8; ni++)
            #pragma unroll
            for (int cc = 0; cc < 2; cc++)
                cn[ni*2+cc] = g_onorm[colBase + cw + ni*8 + tig*2 + cc];
        #pragma unroll
        for (int mi = 0; mi < 2; mi++)
            #pragma unroll
            for (int ni = 0; ni < 8; ni++)
                #pragma unroll
                for (int rr = 0; rr < 2; rr++)
                    #pragma unroll
                    for (int cc = 0; cc < 2; cc++){
                        int lm = rw + mi*16 + rr*8 + gid;
                        int ln = cw + ni*8 + tig*2 + cc;
                        float d = fmaxf(rn[mi*2+rr] + cn[ni*2+cc]
                                        - 2.f * acc[mi][ni][rr*2+cc], 0.f);
                        Et16[lm*LDEH + ln] = __float2half(exp_neg(d * invs));
                    }
    }

    asm volatile("cp.async.wait_group 0;\n" ::: "memory");
    __syncthreads();                           // Fea tiles + Et16 visible

    // ---- phase 2: feature Gram, fp32 SIMT (RN accumulate — bias-free) ----
    const float* FAt = smem;                   // [64][128]
    const float* FBt = smem + 8192;            // [64][128]
    const int tx = tid & 15, ty = tid >> 4;

    float fac[8][8];
    #pragma unroll
    for (int m = 0; m < 8; m++)
        #pragma unroll
        for (int n = 0; n < 8; n++) fac[m][n] = 0.f;

    for (int kb = 0; kb < DF; kb += 16){
        #pragma unroll
        for (int k16 = 0; k16 < 16; k16++){
            const int k = kb + k16;
            float a[8], b[8];
            #pragma unroll
            for (int m = 0; m < 8; m++) a[m] = FAt[k*128 + ty*8 + m];
            #pragma unroll
            for (int n = 0; n < 8; n++) b[n] = FBt[k*128 + tx*8 + n];
            #pragma unroll
            for (int m = 0; m < 8; m++)
                #pragma unroll
                for (int n = 0; n < 8; n++) fac[m][n] += a[m] * b[n];
        }
    }

    // ---- final epilogue: per-TILE classification ----
    const bool diagTile = (bi == bj);
    const bool sdTile   = (bj - bi == 32);     // ci - ri == NHALF  <=>  ln == lm
    const int  cls      = (bj < 32) ? 0 : ((bi >= 32) ? 1 : 2);
    const float mult    = diagTile ? 1.f : 2.f;

    float fnr[8], fnc[8];
    #pragma unroll
    for (int m = 0; m < 8; m++) fnr[m] = g_fnorm[rowBase + ty*8 + m];
    #pragma unroll
    for (int n = 0; n < 8; n++) fnc[n] = g_fnorm[colBase + tx*8 + n];

    float s = 0.f, sd = 0.f;
    #pragma unroll
    for (int m = 0; m < 8; m++){
        const int lm = ty*8 + m;
        #pragma unroll
        for (int n = 0; n < 8; n++){
            const int ln = tx*8 + n;
            if (diagTile && lm == ln) continue;          // diagonal excluded
            float dd = fmaxf(fnr[m] + fnc[n] - 2.f * fac[m][n], 0.f);
            float eo = __half2float(Et16[lm*LDEH + ln]);
            float kv = (1.f - ep) * exp_neg(dd * invs0) * eo + ep * eo;
            s += kv;
            if (sdTile && lm == ln) sd += kv;
        }
    }
    s *= mult;                                  // sd counted once per pair

    #pragma unroll
    for (int off = 16; off; off >>= 1)
        s += __shfl_xor_sync(0xffffffffu, s, off);
    if (sdTile){
        #pragma unroll
        for (int off = 16; off; off >>= 1)
            sd += __shfl_xor_sync(0xffffffffu, sd, off);
    }
    if (lane == 0){
        atomicAdd(&g_acc[cls], (double)s);
        if (sdTile) atomicAdd(&g_acc[3], (double)sd);
    }
}

// ---------------- finalize ----------------
__global__ void fin_kernel(float* __restrict__ out){
    double n = (double)NHALF;
    double denom = n * (n - 1.0);
    double xx = g_acc[0] / denom;
    double yy = g_acc[1] / denom;
    double xy = (0.5 * g_acc[2] - g_acc[3]) / denom;
    out[0] = (float)(xx - 2.0 * xy + yy);
}

// ---------------- launch ----------------
extern "C" void kernel_launch(void* const* d_in, const int* in_sizes, int n_in,
                              void* d_out, int out_size){
    const float* Xs  = (const float*)d_in[0];
    const float* Xt  = (const float*)d_in[1];
    const float* W1  = (const float*)d_in[2];
    const float* b1  = (const float*)d_in[3];
    const float* W2  = (const float*)d_in[4];
    const float* b2  = (const float*)d_in[5];
    const float* W3  = (const float*)d_in[6];
    const float* b3  = (const float*)d_in[7];
    const float* W4  = (const float*)d_in[8];
    const float* b4  = (const float*)d_in[9];
    const float* eps = (const float*)d_in[10];
    const float* sg  = (const float*)d_in[11];
    const float* sg0 = (const float*)d_in[12];

    init_kernel<<<1, 32>>>(eps, sg, sg0);
    feat_kernel<<<NROWS/32, 256>>>(Xs, Xt, W1, b1, W2, b2, W3, b3, W4, b4);

    cudaFuncSetAttribute(pair_kernel, cudaFuncAttributeMaxDynamicSharedMemorySize, SMEM_BYTES);
    pair_kernel<<<NPAIR, 256, SMEM_BYTES>>>();

    fin_kernel<<<1, 1>>>((float*)d_out);
}

// round 13
// speedup vs baseline: 1.0019x; 1.0019x over previous
#include <cuda_runtime.h>
#include <cuda_bf16.h>
#include <cuda_fp16.h>
#include <math.h>
#include <stdint.h>

#define NROWS 8192
#define NHALF 4096
#define DIN   512
#define DF    64      // feature dim padded (50 -> 64, zeros)
#define DOUT  50
#define HID   10
#define BM    128
#define BN    128
#define KC    64      // phase-1 k-chunk (bf16 elements; 128 B/row)
#define NB    (NROWS/BM)   // 64
#define NPAIR (NB*(NB+1)/2)  // 2080 upper-triangle tiles
#define NCHUNK (DIN/KC)    // 8
#define LDEH  130     // Et fp16 lead dim (halves)

// smem float offsets
#define OFF_A0  0
#define OFF_B0  4096
#define OFF_A1  8192
#define OFF_B1  12288
#define OFF_ET16 16384
#define SMEM_FLOATS (OFF_ET16 + (BM*LDEH)/2)   // 24704
#define SMEM_BYTES  (SMEM_FLOATS * 4)          // 98,816 B -> 2 CTAs/SM

// -------- scratch (no dynamic allocation allowed) --------
__device__ __nv_bfloat16 g_XcatH[NROWS*DIN];  // bf16-rounded concat(Xs,Xt)
__device__ float  g_FeaT[DF*NROWS];      // TRANSPOSED features [k][row], fp32
__device__ float  g_onorm[NROWS];        // norms of bf16-ROUNDED originals
__device__ float  g_fnorm[NROWS];
__device__ double g_acc[4];              // Sx, Sy, Smixed(2*sumKxy), Sdiag_xy
__device__ float  g_par[3];              // ep, 1/sigma, 1/sigma0
__device__ unsigned int g_done;          // completed pair-blocks counter

__device__ __forceinline__ float softplus_f(float x){
    return fmaxf(x, 0.f) + log1pf(expf(-fabsf(x)));
}

// exp(-x) for x >= 0, FMA-pipe only (no MUFU). ~3e-7 relative error.
__device__ __forceinline__ float exp_neg(float x){
    float t = x * -1.4426950408889634f;
    t = fmaxf(t, -125.f);
    float fn = t + 12582912.f;                   // 2^23 + 2^22 round magic
    int   ni = __float_as_int(fn) - 0x4B400000;
    float r  = t - (fn - 12582912.f);
    float p  = 1.5403530393e-4f;
    p = fmaf(p, r, 1.3333558146e-3f);
    p = fmaf(p, r, 9.6181291076e-3f);
    p = fmaf(p, r, 5.5504108665e-2f);
    p = fmaf(p, r, 2.4022650696e-1f);
    p = fmaf(p, r, 6.9314718056e-1f);
    p = fmaf(p, r, 1.0f);
    return __int_as_float(__float_as_int(p) + (ni << 23));
}

__device__ __forceinline__ void cp16(float* dst, const void* src){
    uint32_t d = (uint32_t)__cvta_generic_to_shared(dst);
    asm volatile("cp.async.cg.shared.global [%0], [%1], 16;\n"
                 :: "r"(d), "l"(src) : "memory");
}
__device__ __forceinline__ void cp_commit(){
    asm volatile("cp.async.commit_group;\n" ::: "memory");
}
__device__ __forceinline__ void ldsm4(uint32_t& r0, uint32_t& r1,
                                      uint32_t& r2, uint32_t& r3, uint32_t addr){
    asm volatile("ldmatrix.sync.aligned.m8n8.x4.shared.b16 {%0,%1,%2,%3}, [%4];"
                 : "=r"(r0), "=r"(r1), "=r"(r2), "=r"(r3) : "r"(addr));
}

// ---------------- featurize: warp per row, 32 rows/block; block 0 also inits ----------------
__global__ __launch_bounds__(256)
void feat_kernel(const float* __restrict__ Xs, const float* __restrict__ Xt,
                 const float* __restrict__ W1, const float* __restrict__ b1,
                 const float* __restrict__ W2, const float* __restrict__ b2,
                 const float* __restrict__ W3, const float* __restrict__ b3,
                 const float* __restrict__ W4, const float* __restrict__ b4,
                 const float* __restrict__ eps, const float* __restrict__ sig,
                 const float* __restrict__ sig0)
{
    __shared__ float sW1[DIN*HID];
    __shared__ float sW2[HID*HID], sW3[HID*HID], sW4[HID*DOUT];
    __shared__ float sb1[HID], sb2[HID], sb3[HID], sb4[DOUT];
    int tid = threadIdx.x;
    if (blockIdx.x == 0 && tid == 0){          // folded init (runs before pair launch)
        g_par[0] = 1.f / (1.f + expf(-eps[0]));
        g_par[1] = 1.f / (sig[0]  * sig[0]);
        g_par[2] = 1.f / (sig0[0] * sig0[0]);
        g_acc[0] = 0.0; g_acc[1] = 0.0; g_acc[2] = 0.0; g_acc[3] = 0.0;
        g_done = 0u;
    }
    for (int i = tid; i < DIN*HID; i += 256) sW1[i] = W1[i];
    for (int i = tid; i < HID*HID; i += 256){ sW2[i] = W2[i]; sW3[i] = W3[i]; }
    for (int i = tid; i < HID*DOUT; i += 256) sW4[i] = W4[i];
    if (tid < HID){ sb1[tid] = b1[tid]; sb2[tid] = b2[tid]; sb3[tid] = b3[tid]; }
    if (tid < DOUT) sb4[tid] = b4[tid];
    __syncthreads();

    int warp = tid >> 5, lane = tid & 31;
    for (int pass = 0; pass < 4; pass++){
        int row = blockIdx.x * 32 + pass * 8 + warp;
        const float* src = (row < NHALF) ? (Xs + (size_t)row * DIN)
                                         : (Xt + (size_t)(row - NHALF) * DIN);
        float acc[HID];
        #pragma unroll
        for (int o = 0; o < HID; o++) acc[o] = 0.f;
        float on = 0.f;
        for (int k = lane; k < DIN; k += 32){
            float x = src[k];
            __nv_bfloat16 xb = __float2bfloat16_rn(x);  // round ONCE; Do exact-for-perturbed
            float xf = __bfloat162float(xb);
            g_XcatH[(size_t)row * DIN + k] = xb;
            on += xf * xf;
            #pragma unroll
            for (int o = 0; o < HID; o++) acc[o] += x * sW1[k*HID + o];
        }
        #pragma unroll
        for (int off = 16; off; off >>= 1){
            on += __shfl_xor_sync(0xffffffffu, on, off);
            #pragma unroll
            for (int o = 0; o < HID; o++)
                acc[o] += __shfl_xor_sync(0xffffffffu, acc[o], off);
        }
        if (lane == 0) g_onorm[row] = on;

        float h1[HID], h2[HID], h3[HID];
        #pragma unroll
        for (int o = 0; o < HID; o++) h1[o] = softplus_f(acc[o] + sb1[o]);
        #pragma unroll
        for (int o = 0; o < HID; o++){
            float t = sb2[o];
            #pragma unroll
            for (int p = 0; p < HID; p++) t += h1[p] * sW2[p*HID + o];
            h2[o] = softplus_f(t);
        }
        #pragma unroll
        for (int o = 0; o < HID; o++){
            float t = sb3[o];
            #pragma unroll
            for (int p = 0; p < HID; p++) t += h2[p] * sW3[p*HID + o];
            h3[o] = softplus_f(t);
        }
        float fn = 0.f;
        for (int c = lane; c < DF; c += 32){
            float v = 0.f;
            if (c < DOUT){
                v = sb4[c];
                #pragma unroll
                for (int p = 0; p < HID; p++) v += h3[p] * sW4[p*DOUT + c];
            }
            g_FeaT[(size_t)c * NROWS + row] = v;   // transposed for phase-2 cp.async
            fn += v * v;
        }
        #pragma unroll
        for (int off = 16; off; off >>= 1)
            fn += __shfl_xor_sync(0xffffffffu, fn, off);
        if (lane == 0) g_fnorm[row] = fn;
    }
}

// ---------------- fused pairwise kernel (packed triangular grid) ----------------
__global__ __launch_bounds__(256, 2)
void pair_kernel(float* __restrict__ out){
    // decode linear block id -> (bi, bj), bj >= bi
    int t = blockIdx.x;
    float nf = (float)NB + 0.5f;
    int bi = (int)(nf - sqrtf(fmaxf(nf*nf - 2.0f*(float)t, 0.f)));
    bi = max(0, min(NB - 1, bi));
    while (bi > 0 && (bi*NB - bi*(bi-1)/2) > t) bi--;
    while (((bi+1)*NB - (bi+1)*bi/2) <= t) bi++;
    int bj = bi + (t - (bi*NB - bi*(bi-1)/2));

    extern __shared__ float smem[];
    const int tid  = threadIdx.x;
    const int lane = tid & 31, warp = tid >> 5;
    const int gid  = lane >> 2, tig = lane & 3;
    const int warpM = warp >> 1, warpN = warp & 1;   // 4 x 2 warp grid
    const int rw = warpM * 32;                 // warp row base (local)
    const int cw = warpN * 64;                 // warp col base (local)
    const int rowBase = bi * BM, colBase = bj * BN;

    // ldmatrix per-thread addressing constants
    const uint32_t smem_sh = (uint32_t)__cvta_generic_to_shared(smem);
    const int msel = lane >> 3, row8 = lane & 7;
    const int aGh = msel >> 1;                 // A: mats [m0-7 g0][m8-15 g0][m0-7 g1][m8-15 g1]
    const int bGh = msel & 1;                  // B: mats [n0 g0][n0 g1][n1 g0][n1 g1]
    uint32_t aRow[2], bRow[4];
    #pragma unroll
    for (int mi = 0; mi < 2; mi++)
        aRow[mi] = (uint32_t)(rw + mi*16 + (msel & 1)*8 + row8) * 128u;
    #pragma unroll
    for (int np = 0; np < 4; np++)
        bRow[np] = (uint32_t)(cw + (2*np + (msel >> 1))*8 + row8) * 128u;

    // ---- phase 1: original-space Gram via bf16 m16n8k16 (K = 512) ----
    float acc[2][8][4];
    #pragma unroll
    for (int mi = 0; mi < 2; mi++)
        #pragma unroll
        for (int ni = 0; ni < 8; ni++)
            #pragma unroll
            for (int r = 0; r < 4; r++) acc[mi][ni][r] = 0.f;

    #pragma unroll
    for (int st = 0; st < 2; st++){
        float* bA = smem + (st ? OFF_A1 : OFF_A0);
        float* bB = smem + (st ? OFF_B1 : OFF_B0);
        int kb = st * KC;
        #pragma unroll
        for (int i = 0; i < 4; i++){
            int idx = tid + i * 256;
            int r = idx >> 3, g = idx & 7;
            int sw = r*32 + (((g ^ (r & 7)) << 2));
            cp16(bA + sw, &g_XcatH[(size_t)(rowBase + r)*DIN + kb + (g << 3)]);
            cp16(bB + sw, &g_XcatH[(size_t)(colBase + r)*DIN + kb + (g << 3)]);
        }
        cp_commit();
    }

    for (int c = 0; c < NCHUNK; c++){
        if (c < NCHUNK - 1) asm volatile("cp.async.wait_group 1;\n" ::: "memory");
        else                asm volatile("cp.async.wait_group 0;\n" ::: "memory");
        __syncthreads();

        const uint32_t baseA = smem_sh + ((c & 1) ? OFF_A1 : OFF_A0) * 4u;
        const uint32_t baseB = smem_sh + ((c & 1) ? OFF_B1 : OFF_B0) * 4u;

        #pragma unroll
        for (int ks = 0; ks < 4; ks++){        // 4 k16-steps per 64-elem chunk
            const int g0 = 2*ks;
            uint32_t a[2][4];
            #pragma unroll
            for (int mi = 0; mi < 2; mi++){
                uint32_t ad = baseA + aRow[mi] + ((uint32_t)((g0 + aGh) ^ row8) << 4);
                ldsm4(a[mi][0], a[mi][1], a[mi][2], a[mi][3], ad);
            }
            uint32_t bfr[8][2];
            #pragma unroll
            for (int np = 0; np < 4; np++){
                uint32_t ad = baseB + bRow[np] + ((uint32_t)((g0 + bGh) ^ row8) << 4);
                ldsm4(bfr[2*np][0], bfr[2*np][1], bfr[2*np+1][0], bfr[2*np+1][1], ad);
            }
            #pragma unroll
            for (int mi = 0; mi < 2; mi++)
                #pragma unroll
                for (int ni = 0; ni < 8; ni++){
                    asm volatile(
                        "mma.sync.aligned.m16n8k16.row.col.f32.bf16.bf16.f32 "
                        "{%0,%1,%2,%3}, {%4,%5,%6,%7}, {%8,%9}, {%0,%1,%2,%3};\n"
                        : "+f"(acc[mi][ni][0]), "+f"(acc[mi][ni][1]),
                          "+f"(acc[mi][ni][2]), "+f"(acc[mi][ni][3])
                        : "r"(a[mi][0]), "r"(a[mi][1]), "r"(a[mi][2]), "r"(a[mi][3]),
                          "r"(bfr[ni][0]), "r"(bfr[ni][1]));
                }
        }
        __syncthreads();     // all warps done reading buf[c&1] before refill

        if (c + 2 < NCHUNK){
            float* bA = smem + ((c & 1) ? OFF_A1 : OFF_A0);
            float* bB = smem + ((c & 1) ? OFF_B1 : OFF_B0);
            int kb = (c + 2) * KC;
            #pragma unroll
            for (int i = 0; i < 4; i++){
                int idx = tid + i * 256;
                int r = idx >> 3, g = idx & 7;
                int sw = r*32 + (((g ^ (r & 7)) << 2));
                cp16(bA + sw, &g_XcatH[(size_t)(rowBase + r)*DIN + kb + (g << 3)]);
                cp16(bB + sw, &g_XcatH[(size_t)(colBase + r)*DIN + kb + (g << 3)]);
            }
            cp_commit();
        }
    }
    // All phase-1 buffers dead now.

    // Prefetch BOTH transposed Fea tiles into [0,16384) floats (overlaps Et epilogue).
    #pragma unroll
    for (int i = 0; i < 8; i++){
        int idx = tid + i * 256;
        int k = idx >> 5, gr = (idx & 31) << 2;
        cp16(smem + k*128 + gr,        &g_FeaT[(size_t)k*NROWS + rowBase + gr]);
        cp16(smem + 8192 + k*128 + gr, &g_FeaT[(size_t)k*NROWS + colBase + gr]);
    }
    cp_commit();

    const float ep    = g_par[0];
    const float invs  = g_par[1];
    const float invs0 = g_par[2];
    __half* Et16 = (__half*)(smem + OFF_ET16); // [128][LDEH] halves

    {   // phase-1 epilogue: Do -> e_org, stage into Et16 (fragment -> (row,col))
        float rn[4], cn[16];
        #pragma unroll
        for (int mi = 0; mi < 2; mi++)
            #pragma unroll
            for (int rr = 0; rr < 2; rr++)
                rn[mi*2+rr] = g_onorm[rowBase + rw + mi*16 + rr*8 + gid];
        #pragma unroll
        for (int ni = 0; ni < 8; ni++)
            #pragma unroll
            for (int cc = 0; cc < 2; cc++)
                cn[ni*2+cc] = g_onorm[colBase + cw + ni*8 + tig*2 + cc];
        #pragma unroll
        for (int mi = 0; mi < 2; mi++)
            #pragma unroll
            for (int ni = 0; ni < 8; ni++)
                #pragma unroll
                for (int rr = 0; rr < 2; rr++)
                    #pragma unroll
                    for (int cc = 0; cc < 2; cc++){
                        int lm = rw + mi*16 + rr*8 + gid;
                        int ln = cw + ni*8 + tig*2 + cc;
                        float d = fmaxf(rn[mi*2+rr] + cn[ni*2+cc]
                                        - 2.f * acc[mi][ni][rr*2+cc], 0.f);
                        Et16[lm*LDEH + ln] = __float2half(exp_neg(d * invs));
                    }
    }

    asm volatile("cp.async.wait_group 0;\n" ::: "memory");
    __syncthreads();                           // Fea tiles + Et16 visible

    // ---- phase 2: feature Gram, fp32 SIMT (RN accumulate — bias-free) ----
    const float* FAt = smem;                   // [64][128]
    const float* FBt = smem + 8192;            // [64][128]
    const int tx = tid & 15, ty = tid >> 4;

    float fac[8][8];
    #pragma unroll
    for (int m = 0; m < 8; m++)
        #pragma unroll
        for (int n = 0; n < 8; n++) fac[m][n] = 0.f;

    for (int kb = 0; kb < DF; kb += 16){
        #pragma unroll
        for (int k16 = 0; k16 < 16; k16++){
            const int k = kb + k16;
            float a[8], b[8];
            #pragma unroll
            for (int m = 0; m < 8; m++) a[m] = FAt[k*128 + ty*8 + m];
            #pragma unroll
            for (int n = 0; n < 8; n++) b[n] = FBt[k*128 + tx*8 + n];
            #pragma unroll
            for (int m = 0; m < 8; m++)
                #pragma unroll
                for (int n = 0; n < 8; n++) fac[m][n] += a[m] * b[n];
        }
    }

    // ---- final epilogue: per-TILE classification ----
    const bool diagTile = (bi == bj);
    const bool sdTile   = (bj - bi == 32);     // ci - ri == NHALF  <=>  ln == lm
    const int  cls      = (bj < 32) ? 0 : ((bi >= 32) ? 1 : 2);
    const float mult    = diagTile ? 1.f : 2.f;

    float fnr[8], fnc[8];
    #pragma unroll
    for (int m = 0; m < 8; m++) fnr[m] = g_fnorm[rowBase + ty*8 + m];
    #pragma unroll
    for (int n = 0; n < 8; n++) fnc[n] = g_fnorm[colBase + tx*8 + n];

    float s = 0.f, sd = 0.f;
    #pragma unroll
    for (int m = 0; m < 8; m++){
        const int lm = ty*8 + m;
        #pragma unroll
        for (int n = 0; n < 8; n++){
            const int ln = tx*8 + n;
            if (diagTile && lm == ln) continue;          // diagonal excluded
            float dd = fmaxf(fnr[m] + fnc[n] - 2.f * fac[m][n], 0.f);
            float eo = __half2float(Et16[lm*LDEH + ln]);
            float kv = (1.f - ep) * exp_neg(dd * invs0) * eo + ep * eo;
            s += kv;
            if (sdTile && lm == ln) sd += kv;
        }
    }
    s *= mult;                                  // sd counted once per pair

    #pragma unroll
    for (int off = 16; off; off >>= 1)
        s += __shfl_xor_sync(0xffffffffu, s, off);
    if (sdTile){
        #pragma unroll
        for (int off = 16; off; off >>= 1)
            sd += __shfl_xor_sync(0xffffffffu, sd, off);
    }
    if (lane == 0){
        atomicAdd(&g_acc[cls], (double)s);
        if (sdTile) atomicAdd(&g_acc[3], (double)sd);
    }

    // ---- folded finalize: last block to finish computes mmd2 ----
    __syncthreads();                            // all this block's atomics issued
    if (tid == 0){
        __threadfence();                        // publish g_acc updates
        unsigned int old = atomicAdd(&g_done, 1u);
        if (old == NPAIR - 1u){                 // last block: all others fenced+counted
            double n = (double)NHALF;
            double denom = n * (n - 1.0);
            double xx = g_acc[0] / denom;
            double yy = g_acc[1] / denom;
            double xy = (0.5 * g_acc[2] - g_acc[3]) / denom;
            out[0] = (float)(xx - 2.0 * xy + yy);
        }
    }
}

// ---------------- launch ----------------
extern "C" void kernel_launch(void* const* d_in, const int* in_sizes, int n_in,
                              void* d_out, int out_size){
    const float* Xs  = (const float*)d_in[0];
    const float* Xt  = (const float*)d_in[1];
    const float* W1  = (const float*)d_in[2];
    const float* b1  = (const float*)d_in[3];
    const float* W2  = (const float*)d_in[4];
    const float* b2  = (const float*)d_in[5];
    const float* W3  = (const float*)d_in[6];
    const float* b3  = (const float*)d_in[7];
    const float* W4  = (const float*)d_in[8];
    const float* b4  = (const float*)d_in[9];
    const float* eps = (const float*)d_in[10];
    const float* sg  = (const float*)d_in[11];
    const float* sg0 = (const float*)d_in[12];

    feat_kernel<<<NROWS/32, 256>>>(Xs, Xt, W1, b1, W2, b2, W3, b3, W4, b4,
                                   eps, sg, sg0);

    cudaFuncSetAttribute(pair_kernel, cudaFuncAttributeMaxDynamicSharedMemorySize, SMEM_BYTES);
    pair_kernel<<<NPAIR, 256, SMEM_BYTES>>>((float*)d_out);
}

// round 14
// speedup vs baseline: 1.0051x; 1.0031x over previous
#include <cuda_runtime.h>
#include <cuda_bf16.h>
#include <cuda_fp16.h>
#include <math.h>
#include <stdint.h>

#define NROWS 8192
#define NHALF 4096
#define DIN   512
#define DF    64      // feature dim padded (50 -> 64, zeros)
#define DOUT  50
#define HID   10
#define BM    128
#define BN    128
#define KC    64      // phase-1 k-chunk (bf16 elements; 128 B/row)
#define NB    (NROWS/BM)   // 64
#define NPAIR (NB*(NB+1)/2)  // 2080 upper-triangle tiles
#define NCHUNK (DIN/KC)    // 8
#define LDEH  130     // Et fp16 lead dim (halves)

// smem float offsets
#define OFF_A0  0
#define OFF_B0  4096
#define OFF_A1  8192
#define OFF_B1  12288
#define OFF_ET16 16384
#define SMEM_FLOATS (OFF_ET16 + (BM*LDEH)/2)   // 24704
#define SMEM_BYTES  (SMEM_FLOATS * 4)          // 98,816 B -> 2 CTAs/SM

// -------- scratch (no dynamic allocation allowed) --------
__device__ __nv_bfloat16 g_XcatH[NROWS*DIN];  // bf16-rounded concat(Xs,Xt)
__device__ float  g_FeaT[DF*NROWS];      // TRANSPOSED features [k][row], fp32
__device__ float  g_onorm[NROWS];        // norms of bf16-ROUNDED originals
__device__ float  g_fnorm[NROWS];
__device__ double g_acc[4];              // Sx, Sy, Smixed(2*sumKxy), Sdiag_xy
__device__ float  g_par[3];              // ep, 1/sigma, 1/sigma0
__device__ unsigned int g_done;          // completed pair-blocks counter

__device__ __forceinline__ float softplus_f(float x){
    return fmaxf(x, 0.f) + log1pf(expf(-fabsf(x)));
}

// exp(-x) for x >= 0, FMA-pipe only (no MUFU). ~3e-7 relative error.
__device__ __forceinline__ float exp_neg(float x){
    float t = x * -1.4426950408889634f;
    t = fmaxf(t, -125.f);
    float fn = t + 12582912.f;                   // 2^23 + 2^22 round magic
    int   ni = __float_as_int(fn) - 0x4B400000;
    float r  = t - (fn - 12582912.f);
    float p  = 1.5403530393e-4f;
    p = fmaf(p, r, 1.3333558146e-3f);
    p = fmaf(p, r, 9.6181291076e-3f);
    p = fmaf(p, r, 5.5504108665e-2f);
    p = fmaf(p, r, 2.4022650696e-1f);
    p = fmaf(p, r, 6.9314718056e-1f);
    p = fmaf(p, r, 1.0f);
    return __int_as_float(__float_as_int(p) + (ni << 23));
}

__device__ __forceinline__ void cp16(float* dst, const void* src){
    uint32_t d = (uint32_t)__cvta_generic_to_shared(dst);
    asm volatile("cp.async.cg.shared.global [%0], [%1], 16;\n"
                 :: "r"(d), "l"(src) : "memory");
}
__device__ __forceinline__ void cp_commit(){
    asm volatile("cp.async.commit_group;\n" ::: "memory");
}
__device__ __forceinline__ void ldsm4(uint32_t& r0, uint32_t& r1,
                                      uint32_t& r2, uint32_t& r3, uint32_t addr){
    asm volatile("ldmatrix.sync.aligned.m8n8.x4.shared.b16 {%0,%1,%2,%3}, [%4];"
                 : "=r"(r0), "=r"(r1), "=r"(r2), "=r"(r3) : "r"(addr));
}

// ---------------- featurize: warp per row, 32 rows/block; block 0 also inits ----------------
__global__ __launch_bounds__(256)
void feat_kernel(const float* __restrict__ Xs, const float* __restrict__ Xt,
                 const float* __restrict__ W1, const float* __restrict__ b1,
                 const float* __restrict__ W2, const float* __restrict__ b2,
                 const float* __restrict__ W3, const float* __restrict__ b3,
                 const float* __restrict__ W4, const float* __restrict__ b4,
                 const float* __restrict__ eps, const float* __restrict__ sig,
                 const float* __restrict__ sig0)
{
    __shared__ float sW1[DIN*HID];
    __shared__ float sW2[HID*HID], sW3[HID*HID], sW4[HID*DOUT];
    __shared__ float sb1[HID], sb2[HID], sb3[HID], sb4[DOUT];
    int tid = threadIdx.x;
    if (blockIdx.x == 0 && tid == 0){          // folded init (runs before pair launch)
        g_par[0] = 1.f / (1.f + expf(-eps[0]));
        g_par[1] = 1.f / (sig[0]  * sig[0]);
        g_par[2] = 1.f / (sig0[0] * sig0[0]);
        g_acc[0] = 0.0; g_acc[1] = 0.0; g_acc[2] = 0.0; g_acc[3] = 0.0;
        g_done = 0u;
    }
    for (int i = tid; i < DIN*HID; i += 256) sW1[i] = W1[i];
    for (int i = tid; i < HID*HID; i += 256){ sW2[i] = W2[i]; sW3[i] = W3[i]; }
    for (int i = tid; i < HID*DOUT; i += 256) sW4[i] = W4[i];
    if (tid < HID){ sb1[tid] = b1[tid]; sb2[tid] = b2[tid]; sb3[tid] = b3[tid]; }
    if (tid < DOUT) sb4[tid] = b4[tid];
    __syncthreads();

    int warp = tid >> 5, lane = tid & 31;
    for (int pass = 0; pass < 4; pass++){
        int row = blockIdx.x * 32 + pass * 8 + warp;
        const float* src = (row < NHALF) ? (Xs + (size_t)row * DIN)
                                         : (Xt + (size_t)(row - NHALF) * DIN);
        float acc[HID];
        #pragma unroll
        for (int o = 0; o < HID; o++) acc[o] = 0.f;
        float on = 0.f;
        for (int k = lane; k < DIN; k += 32){
            float x = src[k];
            __nv_bfloat16 xb = __float2bfloat16_rn(x);  // round ONCE; Do exact-for-perturbed
            float xf = __bfloat162float(xb);
            g_XcatH[(size_t)row * DIN + k] = xb;
            on += xf * xf;
            #pragma unroll
            for (int o = 0; o < HID; o++) acc[o] += x * sW1[k*HID + o];
        }
        #pragma unroll
        for (int off = 16; off; off >>= 1){
            on += __shfl_xor_sync(0xffffffffu, on, off);
            #pragma unroll
            for (int o = 0; o < HID; o++)
                acc[o] += __shfl_xor_sync(0xffffffffu, acc[o], off);
        }
        if (lane == 0) g_onorm[row] = on;

        float h1[HID], h2[HID], h3[HID];
        #pragma unroll
        for (int o = 0; o < HID; o++) h1[o] = softplus_f(acc[o] + sb1[o]);
        #pragma unroll
        for (int o = 0; o < HID; o++){
            float t = sb2[o];
            #pragma unroll
            for (int p = 0; p < HID; p++) t += h1[p] * sW2[p*HID + o];
            h2[o] = softplus_f(t);
        }
        #pragma unroll
        for (int o = 0; o < HID; o++){
            float t = sb3[o];
            #pragma unroll
            for (int p = 0; p < HID; p++) t += h2[p] * sW3[p*HID + o];
            h3[o] = softplus_f(t);
        }
        float fn = 0.f;
        for (int c = lane; c < DF; c += 32){
            float v = 0.f;
            if (c < DOUT){
                v = sb4[c];
                #pragma unroll
                for (int p = 0; p < HID; p++) v += h3[p] * sW4[p*DOUT + c];
            }
            g_FeaT[(size_t)c * NROWS + row] = v;   // transposed for phase-2 cp.async
            fn += v * v;
        }
        #pragma unroll
        for (int off = 16; off; off >>= 1)
            fn += __shfl_xor_sync(0xffffffffu, fn, off);
        if (lane == 0) g_fnorm[row] = fn;
    }
}

// ---------------- fused pairwise kernel (packed triangular grid) ----------------
__global__ __launch_bounds__(256, 2)
void pair_kernel(float* __restrict__ out){
    // decode linear block id -> (bi, bj), bj >= bi
    int t = blockIdx.x;
    float nf = (float)NB + 0.5f;
    int bi = (int)(nf - sqrtf(fmaxf(nf*nf - 2.0f*(float)t, 0.f)));
    bi = max(0, min(NB - 1, bi));
    while (bi > 0 && (bi*NB - bi*(bi-1)/2) > t) bi--;
    while (((bi+1)*NB - (bi+1)*bi/2) <= t) bi++;
    int bj = bi + (t - (bi*NB - bi*(bi-1)/2));

    extern __shared__ float smem[];
    const int tid  = threadIdx.x;
    const int lane = tid & 31, warp = tid >> 5;
    const int gid  = lane >> 2, tig = lane & 3;
    const int warpM = warp >> 1, warpN = warp & 1;   // 4 x 2 warp grid
    const int rw = warpM * 32;                 // warp row base (local)
    const int cw = warpN * 64;                 // warp col base (local)
    const int rowBase = bi * BM, colBase = bj * BN;

    // ldmatrix per-thread addressing constants
    const uint32_t smem_sh = (uint32_t)__cvta_generic_to_shared(smem);
    const int msel = lane >> 3, row8 = lane & 7;
    const int aGh = msel >> 1;                 // A: mats [m0-7 g0][m8-15 g0][m0-7 g1][m8-15 g1]
    const int bGh = msel & 1;                  // B: mats [n0 g0][n0 g1][n1 g0][n1 g1]
    uint32_t aRow[2], bRow[4];
    #pragma unroll
    for (int mi = 0; mi < 2; mi++)
        aRow[mi] = (uint32_t)(rw + mi*16 + (msel & 1)*8 + row8) * 128u;
    #pragma unroll
    for (int np = 0; np < 4; np++)
        bRow[np] = (uint32_t)(cw + (2*np + (msel >> 1))*8 + row8) * 128u;

    // ---- phase 1: original-space Gram via bf16 m16n8k16 (K = 512) ----
    float acc[2][8][4];
    #pragma unroll
    for (int mi = 0; mi < 2; mi++)
        #pragma unroll
        for (int ni = 0; ni < 8; ni++)
            #pragma unroll
            for (int r = 0; r < 4; r++) acc[mi][ni][r] = 0.f;

    #pragma unroll
    for (int st = 0; st < 2; st++){
        float* bA = smem + (st ? OFF_A1 : OFF_A0);
        float* bB = smem + (st ? OFF_B1 : OFF_B0);
        int kb = st * KC;
        #pragma unroll
        for (int i = 0; i < 4; i++){
            int idx = tid + i * 256;
            int r = idx >> 3, g = idx & 7;
            int sw = r*32 + (((g ^ (r & 7)) << 2));
            cp16(bA + sw, &g_XcatH[(size_t)(rowBase + r)*DIN + kb + (g << 3)]);
            cp16(bB + sw, &g_XcatH[(size_t)(colBase + r)*DIN + kb + (g << 3)]);
        }
        cp_commit();
    }

    for (int c = 0; c < NCHUNK; c++){
        if (c < NCHUNK - 1) asm volatile("cp.async.wait_group 1;\n" ::: "memory");
        else                asm volatile("cp.async.wait_group 0;\n" ::: "memory");
        __syncthreads();

        const uint32_t baseA = smem_sh + ((c & 1) ? OFF_A1 : OFF_A0) * 4u;
        const uint32_t baseB = smem_sh + ((c & 1) ? OFF_B1 : OFF_B0) * 4u;

        #pragma unroll
        for (int ks = 0; ks < 4; ks++){        // 4 k16-steps per 64-elem chunk
            const int g0 = 2*ks;
            uint32_t a[2][4];
            #pragma unroll
            for (int mi = 0; mi < 2; mi++){
                uint32_t ad = baseA + aRow[mi] + ((uint32_t)((g0 + aGh) ^ row8) << 4);
                ldsm4(a[mi][0], a[mi][1], a[mi][2], a[mi][3], ad);
            }
            uint32_t bfr[8][2];
            #pragma unroll
            for (int np = 0; np < 4; np++){
                uint32_t ad = baseB + bRow[np] + ((uint32_t)((g0 + bGh) ^ row8) << 4);
                ldsm4(bfr[2*np][0], bfr[2*np][1], bfr[2*np+1][0], bfr[2*np+1][1], ad);
            }
            #pragma unroll
            for (int mi = 0; mi < 2; mi++)
                #pragma unroll
                for (int ni = 0; ni < 8; ni++){
                    asm volatile(
                        "mma.sync.aligned.m16n8k16.row.col.f32.bf16.bf16.f32 "
                        "{%0,%1,%2,%3}, {%4,%5,%6,%7}, {%8,%9}, {%0,%1,%2,%3};\n"
                        : "+f"(acc[mi][ni][0]), "+f"(acc[mi][ni][1]),
                          "+f"(acc[mi][ni][2]), "+f"(acc[mi][ni][3])
                        : "r"(a[mi][0]), "r"(a[mi][1]), "r"(a[mi][2]), "r"(a[mi][3]),
                          "r"(bfr[ni][0]), "r"(bfr[ni][1]));
                }
        }
        __syncthreads();     // all warps done reading buf[c&1] before refill

        if (c + 2 < NCHUNK){
            float* bA = smem + ((c & 1) ? OFF_A1 : OFF_A0);
            float* bB = smem + ((c & 1) ? OFF_B1 : OFF_B0);
            int kb = (c + 2) * KC;
            #pragma unroll
            for (int i = 0; i < 4; i++){
                int idx = tid + i * 256;
                int r = idx >> 3, g = idx & 7;
                int sw = r*32 + (((g ^ (r & 7)) << 2));
                cp16(bA + sw, &g_XcatH[(size_t)(rowBase + r)*DIN + kb + (g << 3)]);
                cp16(bB + sw, &g_XcatH[(size_t)(colBase + r)*DIN + kb + (g << 3)]);
            }
            cp_commit();
        }
    }
    // All phase-1 buffers dead now.

    // Prefetch BOTH transposed Fea tiles into [0,16384) floats (overlaps Et epilogue).
    #pragma unroll
    for (int i = 0; i < 8; i++){
        int idx = tid + i * 256;
        int k = idx >> 5, gr = (idx & 31) << 2;
        cp16(smem + k*128 + gr,        &g_FeaT[(size_t)k*NROWS + rowBase + gr]);
        cp16(smem + 8192 + k*128 + gr, &g_FeaT[(size_t)k*NROWS + colBase + gr]);
    }
    cp_commit();

    const float ep    = g_par[0];
    const float invs  = g_par[1];
    const float invs0 = g_par[2];
    __half* Et16 = (__half*)(smem + OFF_ET16); // [128][LDEH] halves

    {   // phase-1 epilogue: Do -> e_org, stage into Et16 (fragment -> (row,col))
        float rn[4], cn[16];
        #pragma unroll
        for (int mi = 0; mi < 2; mi++)
            #pragma unroll
            for (int rr = 0; rr < 2; rr++)
                rn[mi*2+rr] = g_onorm[rowBase + rw + mi*16 + rr*8 + gid];
        #pragma unroll
        for (int ni = 0; ni < 8; ni++)
            #pragma unroll
            for (int cc = 0; cc < 2; cc++)
                cn[ni*2+cc] = g_onorm[colBase + cw + ni*8 + tig*2 + cc];
        #pragma unroll
        for (int mi = 0; mi < 2; mi++)
            #pragma unroll
            for (int ni = 0; ni < 8; ni++)
                #pragma unroll
                for (int rr = 0; rr < 2; rr++)
                    #pragma unroll
                    for (int cc = 0; cc < 2; cc++){
                        int lm = rw + mi*16 + rr*8 + gid;
                        int ln = cw + ni*8 + tig*2 + cc;
                        float d = fmaxf(rn[mi*2+rr] + cn[ni*2+cc]
                                        - 2.f * acc[mi][ni][rr*2+cc], 0.f);
                        Et16[lm*LDEH + ln] = __float2half(exp_neg(d * invs));
                    }
    }

    asm volatile("cp.async.wait_group 0;\n" ::: "memory");
    __syncthreads();                           // Fea tiles + Et16 visible

    // ---- phase 2: feature Gram, fp32 SIMT (RN accumulate — bias-free),
    //      explicit float4 smem loads (4x fewer L1 wavefronts) ----
    const float* FAt = smem;                   // [64][128]
    const float* FBt = smem + 8192;            // [64][128]
    const int tx = tid & 15, ty = tid >> 4;

    float fac[8][8];
    #pragma unroll
    for (int m = 0; m < 8; m++)
        #pragma unroll
        for (int n = 0; n < 8; n++) fac[m][n] = 0.f;

    for (int kb = 0; kb < DF; kb += 16){
        #pragma unroll
        for (int k16 = 0; k16 < 16; k16++){
            const int k = kb + k16;
            float4 a0 = *(const float4*)&FAt[k*128 + ty*8];
            float4 a1 = *(const float4*)&FAt[k*128 + ty*8 + 4];
            float4 b0 = *(const float4*)&FBt[k*128 + tx*8];
            float4 b1 = *(const float4*)&FBt[k*128 + tx*8 + 4];
            float a[8] = {a0.x, a0.y, a0.z, a0.w, a1.x, a1.y, a1.z, a1.w};
            float b[8] = {b0.x, b0.y, b0.z, b0.w, b1.x, b1.y, b1.z, b1.w};
            #pragma unroll
            for (int m = 0; m < 8; m++)
                #pragma unroll
                for (int n = 0; n < 8; n++) fac[m][n] += a[m] * b[n];
        }
    }

    // ---- final epilogue: per-TILE classification; Et16 read as packed half2 ----
    const bool diagTile = (bi == bj);
    const bool sdTile   = (bj - bi == 32);     // ci - ri == NHALF  <=>  ln == lm
    const int  cls      = (bj < 32) ? 0 : ((bi >= 32) ? 1 : 2);
    const float mult    = diagTile ? 1.f : 2.f;

    float fnr[8], fnc[8];
    #pragma unroll
    for (int m = 0; m < 8; m++) fnr[m] = g_fnorm[rowBase + ty*8 + m];
    #pragma unroll
    for (int n = 0; n < 8; n++) fnc[n] = g_fnorm[colBase + tx*8 + n];

    float s = 0.f, sd = 0.f;
    #pragma unroll
    for (int m = 0; m < 8; m++){
        const int lm = ty*8 + m;
        // vectorized Et row read: 8 halves as 4 x half2 (4-byte aligned)
        float eor[8];
        #pragma unroll
        for (int j = 0; j < 4; j++){
            __half2 h2 = *(const __half2*)&Et16[lm*LDEH + tx*8 + 2*j];
            float2 f2 = __half22float2(h2);
            eor[2*j]   = f2.x;
            eor[2*j+1] = f2.y;
        }
        #pragma unroll
        for (int n = 0; n < 8; n++){
            const int ln = tx*8 + n;
            if (diagTile && lm == ln) continue;          // diagonal excluded
            float dd = fmaxf(fnr[m] + fnc[n] - 2.f * fac[m][n], 0.f);
            float eo = eor[n];
            float kv = (1.f - ep) * exp_neg(dd * invs0) * eo + ep * eo;
            s += kv;
            if (sdTile && lm == ln) sd += kv;
        }
    }
    s *= mult;                                  // sd counted once per pair

    #pragma unroll
    for (int off = 16; off; off >>= 1)
        s += __shfl_xor_sync(0xffffffffu, s, off);
    if (sdTile){
        #pragma unroll
        for (int off = 16; off; off >>= 1)
            sd += __shfl_xor_sync(0xffffffffu, sd, off);
    }
    if (lane == 0){
        atomicAdd(&g_acc[cls], (double)s);
        if (sdTile) atomicAdd(&g_acc[3], (double)sd);
    }

    // ---- folded finalize: last block to finish computes mmd2 ----
    __syncthreads();                            // all this block's atomics issued
    if (tid == 0){
        __threadfence();                        // publish g_acc updates
        unsigned int old = atomicAdd(&g_done, 1u);
        if (old == NPAIR - 1u){                 // last block: all others fenced+counted
            double n = (double)NHALF;
            double denom = n * (n - 1.0);
            double xx = g_acc[0] / denom;
            double yy = g_acc[1] / denom;
            double xy = (0.5 * g_acc[2] - g_acc[3]) / denom;
            out[0] = (float)(xx - 2.0 * xy + yy);
        }
    }
}

// ---------------- launch ----------------
extern "C" void kernel_launch(void* const* d_in, const int* in_sizes, int n_in,
                              void* d_out, int out_size){
    const float* Xs  = (const float*)d_in[0];
    const float* Xt  = (const float*)d_in[1];
    const float* W1  = (const float*)d_in[2];
    const float* b1  = (const float*)d_in[3];
    const float* W2  = (const float*)d_in[4];
    const float* b2  = (const float*)d_in[5];
    const float* W3  = (const float*)d_in[6];
    const float* b3  = (const float*)d_in[7];
    const float* W4  = (const float*)d_in[8];
    const float* b4  = (const float*)d_in[9];
    const float* eps = (const float*)d_in[10];
    const float* sg  = (const float*)d_in[11];
    const float* sg0 = (const float*)d_in[12];

    feat_kernel<<<NROWS/32, 256>>>(Xs, Xt, W1, b1, W2, b2, W3, b3, W4, b4,
                                   eps, sg, sg0);

    cudaFuncSetAttribute(pair_kernel, cudaFuncAttributeMaxDynamicSharedMemorySize, SMEM_BYTES);
    pair_kernel<<<NPAIR, 256, SMEM_BYTES>>>((float*)d_out);
}

// round 15
// speedup vs baseline: 1.0131x; 1.0080x over previous
#include <cuda_runtime.h>
#include <cuda_bf16.h>
#include <cuda_fp16.h>
#include <math.h>
#include <stdint.h>

#define NROWS 8192
#define NHALF 4096
#define DIN   512
#define DF    64      // feature dim padded (50 -> 64, zeros)
#define DOUT  50
#define HID   10
#define BM    128
#define BN    128
#define KC    64      // phase-1 k-chunk (bf16 elements; 128 B/row)
#define NB    (NROWS/BM)   // 64
#define NPAIR (NB*(NB+1)/2)  // 2080 upper-triangle tiles
#define NCHUNK (DIN/KC)    // 8
#define LDEH  130     // Et fp16 lead dim (halves)

// smem float offsets.
// Phase-1: 3 bf16 tile stages (A+B = 8192 floats each) at 0 / 8192 / 16384.
// Stage 2 overlaps the Et16 region (dead until after the chunk loop).
// Phase-2 Fea tiles reuse stages 0+1 ([0,16384)). Et16 at 16384. Norms at 24704.
#define OFF_ET16 16384
#define OFF_NRM  24704                          // on_r[128] on_c[128] fn_r[128] fn_c[128]
#define SMEM_FLOATS (OFF_NRM + 512)             // 25216
#define SMEM_BYTES  (SMEM_FLOATS * 4)           // 100,864 B -> 2 CTAs/SM

// -------- scratch (no dynamic allocation allowed) --------
__device__ __nv_bfloat16 g_XcatH[NROWS*DIN];  // bf16-rounded concat(Xs,Xt)
__device__ float  g_FeaT[DF*NROWS];      // TRANSPOSED features [k][row], fp32
__device__ float  g_onorm[NROWS];        // norms of bf16-ROUNDED originals
__device__ float  g_fnorm[NROWS];
__device__ double g_acc[4];              // Sx, Sy, Smixed(2*sumKxy), Sdiag_xy
__device__ float  g_par[3];              // ep, 1/sigma, 1/sigma0
__device__ unsigned int g_done;          // completed pair-blocks counter

__device__ __forceinline__ float softplus_f(float x){
    return fmaxf(x, 0.f) + log1pf(expf(-fabsf(x)));
}

// exp(-x) for x >= 0, FMA-pipe only (no MUFU). ~3e-7 relative error.
__device__ __forceinline__ float exp_neg(float x){
    float t = x * -1.4426950408889634f;
    t = fmaxf(t, -125.f);
    float fn = t + 12582912.f;                   // 2^23 + 2^22 round magic
    int   ni = __float_as_int(fn) - 0x4B400000;
    float r  = t - (fn - 12582912.f);
    float p  = 1.5403530393e-4f;
    p = fmaf(p, r, 1.3333558146e-3f);
    p = fmaf(p, r, 9.6181291076e-3f);
    p = fmaf(p, r, 5.5504108665e-2f);
    p = fmaf(p, r, 2.4022650696e-1f);
    p = fmaf(p, r, 6.9314718056e-1f);
    p = fmaf(p, r, 1.0f);
    return __int_as_float(__float_as_int(p) + (ni << 23));
}

__device__ __forceinline__ void cp16(float* dst, const void* src){
    uint32_t d = (uint32_t)__cvta_generic_to_shared(dst);
    asm volatile("cp.async.cg.shared.global [%0], [%1], 16;\n"
                 :: "r"(d), "l"(src) : "memory");
}
__device__ __forceinline__ void cp_commit(){
    asm volatile("cp.async.commit_group;\n" ::: "memory");
}
__device__ __forceinline__ void ldsm4(uint32_t& r0, uint32_t& r1,
                                      uint32_t& r2, uint32_t& r3, uint32_t addr){
    asm volatile("ldmatrix.sync.aligned.m8n8.x4.shared.b16 {%0,%1,%2,%3}, [%4];"
                 : "=r"(r0), "=r"(r1), "=r"(r2), "=r"(r3) : "r"(addr));
}

// ---------------- featurize: warp per row, 32 rows/block; block 0 also inits ----------------
__global__ __launch_bounds__(256)
void feat_kernel(const float* __restrict__ Xs, const float* __restrict__ Xt,
                 const float* __restrict__ W1, const float* __restrict__ b1,
                 const float* __restrict__ W2, const float* __restrict__ b2,
                 const float* __restrict__ W3, const float* __restrict__ b3,
                 const float* __restrict__ W4, const float* __restrict__ b4,
                 const float* __restrict__ eps, const float* __restrict__ sig,
                 const float* __restrict__ sig0)
{
    __shared__ float sW1[DIN*HID];
    __shared__ float sW2[HID*HID], sW3[HID*HID], sW4[HID*DOUT];
    __shared__ float sb1[HID], sb2[HID], sb3[HID], sb4[DOUT];
    int tid = threadIdx.x;
    if (blockIdx.x == 0 && tid == 0){          // folded init (runs before pair launch)
        g_par[0] = 1.f / (1.f + expf(-eps[0]));
        g_par[1] = 1.f / (sig[0]  * sig[0]);
        g_par[2] = 1.f / (sig0[0] * sig0[0]);
        g_acc[0] = 0.0; g_acc[1] = 0.0; g_acc[2] = 0.0; g_acc[3] = 0.0;
        g_done = 0u;
    }
    for (int i = tid; i < DIN*HID; i += 256) sW1[i] = W1[i];
    for (int i = tid; i < HID*HID; i += 256){ sW2[i] = W2[i]; sW3[i] = W3[i]; }
    for (int i = tid; i < HID*DOUT; i += 256) sW4[i] = W4[i];
    if (tid < HID){ sb1[tid] = b1[tid]; sb2[tid] = b2[tid]; sb3[tid] = b3[tid]; }
    if (tid < DOUT) sb4[tid] = b4[tid];
    __syncthreads();

    int warp = tid >> 5, lane = tid & 31;
    for (int pass = 0; pass < 4; pass++){
        int row = blockIdx.x * 32 + pass * 8 + warp;
        const float* src = (row < NHALF) ? (Xs + (size_t)row * DIN)
                                         : (Xt + (size_t)(row - NHALF) * DIN);
        float acc[HID];
        #pragma unroll
        for (int o = 0; o < HID; o++) acc[o] = 0.f;
        float on = 0.f;
        for (int k = lane; k < DIN; k += 32){
            float x = src[k];
            __nv_bfloat16 xb = __float2bfloat16_rn(x);  // round ONCE; Do exact-for-perturbed
            float xf = __bfloat162float(xb);
            g_XcatH[(size_t)row * DIN + k] = xb;
            on += xf * xf;
            #pragma unroll
            for (int o = 0; o < HID; o++) acc[o] += x * sW1[k*HID + o];
        }
        #pragma unroll
        for (int off = 16; off; off >>= 1){
            on += __shfl_xor_sync(0xffffffffu, on, off);
            #pragma unroll
            for (int o = 0; o < HID; o++)
                acc[o] += __shfl_xor_sync(0xffffffffu, acc[o], off);
        }
        if (lane == 0) g_onorm[row] = on;

        float h1[HID], h2[HID], h3[HID];
        #pragma unroll
        for (int o = 0; o < HID; o++) h1[o] = softplus_f(acc[o] + sb1[o]);
        #pragma unroll
        for (int o = 0; o < HID; o++){
            float t = sb2[o];
            #pragma unroll
            for (int p = 0; p < HID; p++) t += h1[p] * sW2[p*HID + o];
            h2[o] = softplus_f(t);
        }
        #pragma unroll
        for (int o = 0; o < HID; o++){
            float t = sb3[o];
            #pragma unroll
            for (int p = 0; p < HID; p++) t += h2[p] * sW3[p*HID + o];
            h3[o] = softplus_f(t);
        }
        float fn = 0.f;
        for (int c = lane; c < DF; c += 32){
            float v = 0.f;
            if (c < DOUT){
                v = sb4[c];
                #pragma unroll
                for (int p = 0; p < HID; p++) v += h3[p] * sW4[p*DOUT + c];
            }
            g_FeaT[(size_t)c * NROWS + row] = v;   // transposed for phase-2 cp.async
            fn += v * v;
        }
        #pragma unroll
        for (int off = 16; off; off >>= 1)
            fn += __shfl_xor_sync(0xffffffffu, fn, off);
        if (lane == 0) g_fnorm[row] = fn;
    }
}

// ---------------- fused pairwise kernel (packed triangular grid) ----------------
__global__ __launch_bounds__(256, 2)
void pair_kernel(float* __restrict__ out){
    // decode linear block id -> (bi, bj), bj >= bi
    int t = blockIdx.x;
    float nf = (float)NB + 0.5f;
    int bi = (int)(nf - sqrtf(fmaxf(nf*nf - 2.0f*(float)t, 0.f)));
    bi = max(0, min(NB - 1, bi));
    while (bi > 0 && (bi*NB - bi*(bi-1)/2) > t) bi--;
    while (((bi+1)*NB - (bi+1)*bi/2) <= t) bi++;
    int bj = bi + (t - (bi*NB - bi*(bi-1)/2));

    extern __shared__ float smem[];
    const int tid  = threadIdx.x;
    const int lane = tid & 31, warp = tid >> 5;
    const int gid  = lane >> 2, tig = lane & 3;
    const int warpM = warp >> 1, warpN = warp & 1;   // 4 x 2 warp grid
    const int rw = warpM * 32;                 // warp row base (local)
    const int cw = warpN * 64;                 // warp col base (local)
    const int rowBase = bi * BM, colBase = bj * BN;

    // ldmatrix per-thread addressing constants
    const uint32_t smem_sh = (uint32_t)__cvta_generic_to_shared(smem);
    const int msel = lane >> 3, row8 = lane & 7;
    const int aGh = msel >> 1;
    const int bGh = msel & 1;
    uint32_t aRow[2], bRow[4];
    #pragma unroll
    for (int mi = 0; mi < 2; mi++)
        aRow[mi] = (uint32_t)(rw + mi*16 + (msel & 1)*8 + row8) * 128u;
    #pragma unroll
    for (int np = 0; np < 4; np++)
        bRow[np] = (uint32_t)(cw + (2*np + (msel >> 1))*8 + row8) * 128u;

    // ---- phase 1: original-space Gram via bf16 m16n8k16 (K = 512),
    //      3-stage cp.async pipeline, ONE barrier per chunk ----
    float acc[2][8][4];
    #pragma unroll
    for (int mi = 0; mi < 2; mi++)
        #pragma unroll
        for (int ni = 0; ni < 8; ni++)
            #pragma unroll
            for (int r = 0; r < 4; r++) acc[mi][ni][r] = 0.f;

    // stage bases (floats), rotated each chunk: consume sb0, refill sb2
    int sb0 = 0, sb1 = 8192, sb2 = 16384;

    // prefetch chunks 0 and 1 into stages 0 and 1
    #pragma unroll
    for (int st = 0; st < 2; st++){
        float* base = smem + (st ? 8192 : 0);
        int kb = st * KC;
        #pragma unroll
        for (int i = 0; i < 4; i++){
            int idx = tid + i * 256;           // 1024 16B-granules per A+B pair
            int r = idx >> 3, g = idx & 7;
            int sw = r*32 + (((g ^ (r & 7)) << 2));
            cp16(base + sw,        &g_XcatH[(size_t)(rowBase + r)*DIN + kb + (g << 3)]);
            cp16(base + 4096 + sw, &g_XcatH[(size_t)(colBase + r)*DIN + kb + (g << 3)]);
        }
        cp_commit();
    }

    // stage norms into smem (coalesced; visible after first barrier)
    if (tid < 128){
        smem[OFF_NRM       + tid] = g_onorm[rowBase + tid];
        smem[OFF_NRM + 128 + tid] = g_onorm[colBase + tid];
        smem[OFF_NRM + 256 + tid] = g_fnorm[rowBase + tid];
        smem[OFF_NRM + 384 + tid] = g_fnorm[colBase + tid];
    }

    for (int c = 0; c < NCHUNK; c++){
        if (c < NCHUNK - 1) asm volatile("cp.async.wait_group 1;\n" ::: "memory");
        else                asm volatile("cp.async.wait_group 0;\n" ::: "memory");
        __syncthreads();                       // chunk c ready; stage sb2 fully drained

        const uint32_t baseA = smem_sh + (uint32_t)sb0 * 4u;
        const uint32_t baseB = baseA + 4096u * 4u;

        // refill chunk c+2 into sb2 (no warp can still be reading it)
        if (c + 2 < NCHUNK){
            float* base = smem + sb2;
            int kb = (c + 2) * KC;
            #pragma unroll
            for (int i = 0; i < 4; i++){
                int idx = tid + i * 256;
                int r = idx >> 3, g = idx & 7;
                int sw = r*32 + (((g ^ (r & 7)) << 2));
                cp16(base + sw,        &g_XcatH[(size_t)(rowBase + r)*DIN + kb + (g << 3)]);
                cp16(base + 4096 + sw, &g_XcatH[(size_t)(colBase + r)*DIN + kb + (g << 3)]);
            }
            cp_commit();
        }

        #pragma unroll
        for (int ks = 0; ks < 4; ks++){        // 4 k16-steps per 64-elem chunk
            const int g0 = 2*ks;
            uint32_t a[2][4];
            #pragma unroll
            for (int mi = 0; mi < 2; mi++){
                uint32_t ad = baseA + aRow[mi] + ((uint32_t)((g0 + aGh) ^ row8) << 4);
                ldsm4(a[mi][0], a[mi][1], a[mi][2], a[mi][3], ad);
            }
            uint32_t bfr[8][2];
            #pragma unroll
            for (int np = 0; np < 4; np++){
                uint32_t ad = baseB + bRow[np] + ((uint32_t)((g0 + bGh) ^ row8) << 4);
                ldsm4(bfr[2*np][0], bfr[2*np][1], bfr[2*np+1][0], bfr[2*np+1][1], ad);
            }
            #pragma unroll
            for (int mi = 0; mi < 2; mi++)
                #pragma unroll
                for (int ni = 0; ni < 8; ni++){
                    asm volatile(
                        "mma.sync.aligned.m16n8k16.row.col.f32.bf16.bf16.f32 "
                        "{%0,%1,%2,%3}, {%4,%5,%6,%7}, {%8,%9}, {%0,%1,%2,%3};\n"
                        : "+f"(acc[mi][ni][0]), "+f"(acc[mi][ni][1]),
                          "+f"(acc[mi][ni][2]), "+f"(acc[mi][ni][3])
                        : "r"(a[mi][0]), "r"(a[mi][1]), "r"(a[mi][2]), "r"(a[mi][3]),
                          "r"(bfr[ni][0]), "r"(bfr[ni][1]));
                }
        }

        int tmp = sb0; sb0 = sb1; sb1 = sb2; sb2 = tmp;   // rotate stages
    }
    __syncthreads();                           // all warps done with all stage buffers

    // Prefetch BOTH transposed Fea tiles into [0,16384) floats (overlaps Et epilogue).
    #pragma unroll
    for (int i = 0; i < 8; i++){
        int idx = tid + i * 256;
        int k = idx >> 5, gr = (idx & 31) << 2;
        cp16(smem + k*128 + gr,        &g_FeaT[(size_t)k*NROWS + rowBase + gr]);
        cp16(smem + 8192 + k*128 + gr, &g_FeaT[(size_t)k*NROWS + colBase + gr]);
    }
    cp_commit();

    const float ep    = g_par[0];
    const float invs  = g_par[1];
    const float invs0 = g_par[2];
    __half* Et16 = (__half*)(smem + OFF_ET16); // [128][LDEH] halves
    const float* on_r = smem + OFF_NRM;
    const float* on_c = smem + OFF_NRM + 128;
    const float* fn_r = smem + OFF_NRM + 256;
    const float* fn_c = smem + OFF_NRM + 384;

    {   // phase-1 epilogue: Do -> e_org, stage into Et16 (fragment -> (row,col))
        float rn[4], cn[16];
        #pragma unroll
        for (int mi = 0; mi < 2; mi++)
            #pragma unroll
            for (int rr = 0; rr < 2; rr++)
                rn[mi*2+rr] = on_r[rw + mi*16 + rr*8 + gid];
        #pragma unroll
        for (int ni = 0; ni < 8; ni++)
            #pragma unroll
            for (int cc = 0; cc < 2; cc++)
                cn[ni*2+cc] = on_c[cw + ni*8 + tig*2 + cc];
        #pragma unroll
        for (int mi = 0; mi < 2; mi++)
            #pragma unroll
            for (int ni = 0; ni < 8; ni++)
                #pragma unroll
                for (int rr = 0; rr < 2; rr++)
                    #pragma unroll
                    for (int cc = 0; cc < 2; cc++){
                        int lm = rw + mi*16 + rr*8 + gid;
                        int ln = cw + ni*8 + tig*2 + cc;
                        float d = fmaxf(rn[mi*2+rr] + cn[ni*2+cc]
                                        - 2.f * acc[mi][ni][rr*2+cc], 0.f);
                        Et16[lm*LDEH + ln] = __float2half(exp_neg(d * invs));
                    }
    }

    asm volatile("cp.async.wait_group 0;\n" ::: "memory");
    __syncthreads();                           // Fea tiles + Et16 visible

    // ---- phase 2: feature Gram, fp32 SIMT (RN accumulate — bias-free) ----
    const float* FAt = smem;                   // [64][128]
    const float* FBt = smem + 8192;            // [64][128]
    const int tx = tid & 15, ty = tid >> 4;

    float fac[8][8];
    #pragma unroll
    for (int m = 0; m < 8; m++)
        #pragma unroll
        for (int n = 0; n < 8; n++) fac[m][n] = 0.f;

    for (int kb = 0; kb < DF; kb += 16){
        #pragma unroll
        for (int k16 = 0; k16 < 16; k16++){
            const int k = kb + k16;
            float4 a0 = *(const float4*)&FAt[k*128 + ty*8];
            float4 a1 = *(const float4*)&FAt[k*128 + ty*8 + 4];
            float4 b0 = *(const float4*)&FBt[k*128 + tx*8];
            float4 b1 = *(const float4*)&FBt[k*128 + tx*8 + 4];
            float a[8] = {a0.x, a0.y, a0.z, a0.w, a1.x, a1.y, a1.z, a1.w};
            float b[8] = {b0.x, b0.y, b0.z, b0.w, b1.x, b1.y, b1.z, b1.w};
            #pragma unroll
            for (int m = 0; m < 8; m++)
                #pragma unroll
                for (int n = 0; n < 8; n++) fac[m][n] += a[m] * b[n];
        }
    }

    // ---- final epilogue: per-TILE classification; Et16 read as packed half2 ----
    const bool diagTile = (bi == bj);
    const bool sdTile   = (bj - bi == 32);     // ci - ri == NHALF  <=>  ln == lm
    const int  cls      = (bj < 32) ? 0 : ((bi >= 32) ? 1 : 2);
    const float mult    = diagTile ? 1.f : 2.f;

    float fnr[8], fnc[8];
    #pragma unroll
    for (int m = 0; m < 8; m++) fnr[m] = fn_r[ty*8 + m];
    #pragma unroll
    for (int n = 0; n < 8; n++) fnc[n] = fn_c[tx*8 + n];

    float s = 0.f, sd = 0.f;
    #pragma unroll
    for (int m = 0; m < 8; m++){
        const int lm = ty*8 + m;
        float eor[8];
        #pragma unroll
        for (int j = 0; j < 4; j++){
            __half2 h2 = *(const __half2*)&Et16[lm*LDEH + tx*8 + 2*j];
            float2 f2 = __half22float2(h2);
            eor[2*j]   = f2.x;
            eor[2*j+1] = f2.y;
        }
        #pragma unroll
        for (int n = 0; n < 8; n++){
            const int ln = tx*8 + n;
            if (diagTile && lm == ln) continue;          // diagonal excluded
            float dd = fmaxf(fnr[m] + fnc[n] - 2.f * fac[m][n], 0.f);
            float eo = eor[n];
            float kv = (1.f - ep) * exp_neg(dd * invs0) * eo + ep * eo;
            s += kv;
            if (sdTile && lm == ln) sd += kv;
        }
    }
    s *= mult;                                  // sd counted once per pair

    #pragma unroll
    for (int off = 16; off; off >>= 1)
        s += __shfl_xor_sync(0xffffffffu, s, off);
    if (sdTile){
        #pragma unroll
        for (int off = 16; off; off >>= 1)
            sd += __shfl_xor_sync(0xffffffffu, sd, off);
    }
    if (lane == 0){
        atomicAdd(&g_acc[cls], (double)s);
        if (sdTile) atomicAdd(&g_acc[3], (double)sd);
    }

    // ---- folded finalize: last block to finish computes mmd2 ----
    __syncthreads();                            // all this block's atomics issued
    if (tid == 0){
        __threadfence();                        // publish g_acc updates
        unsigned int old = atomicAdd(&g_done, 1u);
        if (old == NPAIR - 1u){                 // last block: all others fenced+counted
            double n = (double)NHALF;
            double denom = n * (n - 1.0);
            double xx = g_acc[0] / denom;
            double yy = g_acc[1] / denom;
            double xy = (0.5 * g_acc[2] - g_acc[3]) / denom;
            out[0] = (float)(xx - 2.0 * xy + yy);
        }
    }
}

// ---------------- launch ----------------
extern "C" void kernel_launch(void* const* d_in, const int* in_sizes, int n_in,
                              void* d_out, int out_size){
    const float* Xs  = (const float*)d_in[0];
    const float* Xt  = (const float*)d_in[1];
    const float* W1  = (const float*)d_in[2];
    const float* b1  = (const float*)d_in[3];
    const float* W2  = (const float*)d_in[4];
    const float* b2  = (const float*)d_in[5];
    const float* W3  = (const float*)d_in[6];
    const float* b3  = (const float*)d_in[7];
    const float* W4  = (const float*)d_in[8];
    const float* b4  = (const float*)d_in[9];
    const float* eps = (const float*)d_in[10];
    const float* sg  = (const float*)d_in[11];
    const float* sg0 = (const float*)d_in[12];

    feat_kernel<<<NROWS/32, 256>>>(Xs, Xt, W1, b1, W2, b2, W3, b3, W4, b4,
                                   eps, sg, sg0);

    cudaFuncSetAttribute(pair_kernel, cudaFuncAttributeMaxDynamicSharedMemorySize, SMEM_BYTES);
    pair_kernel<<<NPAIR, 256, SMEM_BYTES>>>((float*)d_out);
}

// round 16
// speedup vs baseline: 1.0792x; 1.0652x over previous
#include <cuda_runtime.h>
#include <cuda_bf16.h>
#include <cuda_fp16.h>
#include <math.h>
#include <stdint.h>

#define NROWS 8192
#define NHALF 4096
#define DIN   512
#define DF    64      // feature dim padded (50 -> 64, zeros)
#define DOUT  50
#define HID   10
#define BM    128
#define BN    128
#define KC    64      // phase-1 k-chunk (bf16 elements; 128 B/row)
#define NB    (NROWS/BM)   // 64
#define NPAIR (NB*(NB+1)/2)  // 2080 upper-triangle tiles
#define NCHUNK (DIN/KC)    // 8
#define LDEH  130     // Et fp16 lead dim (halves)

// smem float offsets.
// Phase-1: 3 bf16 tile stages (A+B = 8192 floats each) at 0 / 8192 / 16384.
// Stage 2 overlaps the Et16 region (dead until after the chunk loop).
// Phase-2 Fea tiles reuse stages 0+1 ([0,16384)). Et16 at 16384. Norms at 24704.
#define OFF_ET16 16384
#define OFF_NRM  24704                          // on_r[128] on_c[128] fn_r[128] fn_c[128]
#define SMEM_FLOATS (OFF_NRM + 512)             // 25216
#define SMEM_BYTES  (SMEM_FLOATS * 4)           // 100,864 B -> 2 CTAs/SM

// -------- scratch (no dynamic allocation allowed) --------
__device__ __nv_bfloat16 g_XcatH[NROWS*DIN];  // bf16-rounded concat(Xs,Xt)
__device__ float  g_FeaT[DF*NROWS];      // TRANSPOSED features [k][row], fp32
__device__ float  g_onorm[NROWS];        // norms of bf16-ROUNDED originals
__device__ float  g_fnorm[NROWS];
__device__ double g_acc[4];              // Sx, Sy, Smixed(2*sumKxy), Sdiag_xy
__device__ float  g_par[3];              // ep, 1/sigma, 1/sigma0
__device__ unsigned int g_done;          // completed pair-blocks counter

__device__ __forceinline__ float softplus_f(float x){
    return fmaxf(x, 0.f) + log1pf(expf(-fabsf(x)));
}

// exp(-x) for x >= 0, FMA-pipe only (no MUFU). ~3e-7 relative error.
__device__ __forceinline__ float exp_neg(float x){
    float t = x * -1.4426950408889634f;
    t = fmaxf(t, -125.f);
    float fn = t + 12582912.f;                   // 2^23 + 2^22 round magic
    int   ni = __float_as_int(fn) - 0x4B400000;
    float r  = t - (fn - 12582912.f);
    float p  = 1.5403530393e-4f;
    p = fmaf(p, r, 1.3333558146e-3f);
    p = fmaf(p, r, 9.6181291076e-3f);
    p = fmaf(p, r, 5.5504108665e-2f);
    p = fmaf(p, r, 2.4022650696e-1f);
    p = fmaf(p, r, 6.9314718056e-1f);
    p = fmaf(p, r, 1.0f);
    return __int_as_float(__float_as_int(p) + (ni << 23));
}

__device__ __forceinline__ void cp16(float* dst, const void* src){
    uint32_t d = (uint32_t)__cvta_generic_to_shared(dst);
    asm volatile("cp.async.cg.shared.global [%0], [%1], 16;\n"
                 :: "r"(d), "l"(src) : "memory");
}
__device__ __forceinline__ void cp_commit(){
    asm volatile("cp.async.commit_group;\n" ::: "memory");
}
__device__ __forceinline__ void ldsm4(uint32_t& r0, uint32_t& r1,
                                      uint32_t& r2, uint32_t& r3, uint32_t addr){
    asm volatile("ldmatrix.sync.aligned.m8n8.x4.shared.b16 {%0,%1,%2,%3}, [%4];"
                 : "=r"(r0), "=r"(r1), "=r"(r2), "=r"(r3) : "r"(addr));
}

// ---------------- featurize: warp per row, 32 rows/block; block 0 also inits ----------------
__global__ __launch_bounds__(256)
void feat_kernel(const float* __restrict__ Xs, const float* __restrict__ Xt,
                 const float* __restrict__ W1, const float* __restrict__ b1,
                 const float* __restrict__ W2, const float* __restrict__ b2,
                 const float* __restrict__ W3, const float* __restrict__ b3,
                 const float* __restrict__ W4, const float* __restrict__ b4,
                 const float* __restrict__ eps, const float* __restrict__ sig,
                 const float* __restrict__ sig0)
{
    __shared__ float sW1[DIN*HID];
    __shared__ float sW2[HID*HID], sW3[HID*HID], sW4[HID*DOUT];
    __shared__ float sb1[HID], sb2[HID], sb3[HID], sb4[DOUT];
    int tid = threadIdx.x;
    if (blockIdx.x == 0 && tid == 0){          // folded init (runs before pair launch)
        g_par[0] = 1.f / (1.f + expf(-eps[0]));
        g_par[1] = 1.f / (sig[0]  * sig[0]);
        g_par[2] = 1.f / (sig0[0] * sig0[0]);
        g_acc[0] = 0.0; g_acc[1] = 0.0; g_acc[2] = 0.0; g_acc[3] = 0.0;
        g_done = 0u;
    }
    for (int i = tid; i < DIN*HID; i += 256) sW1[i] = W1[i];
    for (int i = tid; i < HID*HID; i += 256){ sW2[i] = W2[i]; sW3[i] = W3[i]; }
    for (int i = tid; i < HID*DOUT; i += 256) sW4[i] = W4[i];
    if (tid < HID){ sb1[tid] = b1[tid]; sb2[tid] = b2[tid]; sb3[tid] = b3[tid]; }
    if (tid < DOUT) sb4[tid] = b4[tid];
    __syncthreads();

    int warp = tid >> 5, lane = tid & 31;
    for (int pass = 0; pass < 4; pass++){
        int row = blockIdx.x * 32 + pass * 8 + warp;
        const float* src = (row < NHALF) ? (Xs + (size_t)row * DIN)
                                         : (Xt + (size_t)(row - NHALF) * DIN);
        float acc[HID];
        #pragma unroll
        for (int o = 0; o < HID; o++) acc[o] = 0.f;
        float on = 0.f;
        for (int k = lane; k < DIN; k += 32){
            float x = src[k];
            __nv_bfloat16 xb = __float2bfloat16_rn(x);  // round ONCE; Do exact-for-perturbed
            float xf = __bfloat162float(xb);
            g_XcatH[(size_t)row * DIN + k] = xb;
            on += xf * xf;
            #pragma unroll
            for (int o = 0; o < HID; o++) acc[o] += x * sW1[k*HID + o];
        }
        #pragma unroll
        for (int off = 16; off; off >>= 1){
            on += __shfl_xor_sync(0xffffffffu, on, off);
            #pragma unroll
            for (int o = 0; o < HID; o++)
                acc[o] += __shfl_xor_sync(0xffffffffu, acc[o], off);
        }
        if (lane == 0) g_onorm[row] = on;

        float h1[HID], h2[HID], h3[HID];
        #pragma unroll
        for (int o = 0; o < HID; o++) h1[o] = softplus_f(acc[o] + sb1[o]);
        #pragma unroll
        for (int o = 0; o < HID; o++){
            float t = sb2[o];
            #pragma unroll
            for (int p = 0; p < HID; p++) t += h1[p] * sW2[p*HID + o];
            h2[o] = softplus_f(t);
        }
        #pragma unroll
        for (int o = 0; o < HID; o++){
            float t = sb3[o];
            #pragma unroll
            for (int p = 0; p < HID; p++) t += h2[p] * sW3[p*HID + o];
            h3[o] = softplus_f(t);
        }
        float fn = 0.f;
        for (int c = lane; c < DF; c += 32){
            float v = 0.f;
            if (c < DOUT){
                v = sb4[c];
                #pragma unroll
                for (int p = 0; p < HID; p++) v += h3[p] * sW4[p*DOUT + c];
            }
            g_FeaT[(size_t)c * NROWS + row] = v;   // transposed for phase-2 cp.async
            fn += v * v;
        }
        #pragma unroll
        for (int off = 16; off; off >>= 1)
            fn += __shfl_xor_sync(0xffffffffu, fn, off);
        if (lane == 0) g_fnorm[row] = fn;
    }
}

// ---------------- fused pairwise kernel (packed triangular grid) ----------------
__global__ __launch_bounds__(256, 2)
void pair_kernel(float* __restrict__ out){
    // decode linear block id -> (bi, bj), bj >= bi
    int t = blockIdx.x;
    float nf = (float)NB + 0.5f;
    int bi = (int)(nf - sqrtf(fmaxf(nf*nf - 2.0f*(float)t, 0.f)));
    bi = max(0, min(NB - 1, bi));
    while (bi > 0 && (bi*NB - bi*(bi-1)/2) > t) bi--;
    while (((bi+1)*NB - (bi+1)*bi/2) <= t) bi++;
    int bj = bi + (t - (bi*NB - bi*(bi-1)/2));

    extern __shared__ float smem[];
    const int tid  = threadIdx.x;
    const int lane = tid & 31, warp = tid >> 5;
    const int gid  = lane >> 2, tig = lane & 3;
    const int warpM = warp >> 1, warpN = warp & 1;   // 4 x 2 warp grid
    const int rw = warpM * 32;                 // warp row base (local)
    const int cw = warpN * 64;                 // warp col base (local)
    const int rowBase = bi * BM, colBase = bj * BN;

    // ldmatrix per-thread addressing constants
    const uint32_t smem_sh = (uint32_t)__cvta_generic_to_shared(smem);
    const int msel = lane >> 3, row8 = lane & 7;
    const int aGh = msel >> 1;
    const int bGh = msel & 1;
    uint32_t aRow[2], bRow[4];
    #pragma unroll
    for (int mi = 0; mi < 2; mi++)
        aRow[mi] = (uint32_t)(rw + mi*16 + (msel & 1)*8 + row8) * 128u;
    #pragma unroll
    for (int np = 0; np < 4; np++)
        bRow[np] = (uint32_t)(cw + (2*np + (msel >> 1))*8 + row8) * 128u;

    // ---- phase 1: original-space Gram via bf16 m16n8k16 (K = 512),
    //      3-stage cp.async pipeline, ONE barrier per chunk ----
    float acc[2][8][4];
    #pragma unroll
    for (int mi = 0; mi < 2; mi++)
        #pragma unroll
        for (int ni = 0; ni < 8; ni++)
            #pragma unroll
            for (int r = 0; r < 4; r++) acc[mi][ni][r] = 0.f;

    // stage bases (floats), rotated each chunk: consume sb0, refill sb2
    int sb0 = 0, sb1 = 8192, sb2 = 16384;

    // prefetch chunks 0 and 1 into stages 0 and 1
    #pragma unroll
    for (int st = 0; st < 2; st++){
        float* base = smem + (st ? 8192 : 0);
        int kb = st * KC;
        #pragma unroll
        for (int i = 0; i < 4; i++){
            int idx = tid + i * 256;           // 1024 16B-granules per A+B pair
            int r = idx >> 3, g = idx & 7;
            int sw = r*32 + (((g ^ (r & 7)) << 2));
            cp16(base + sw,        &g_XcatH[(size_t)(rowBase + r)*DIN + kb + (g << 3)]);
            cp16(base + 4096 + sw, &g_XcatH[(size_t)(colBase + r)*DIN + kb + (g << 3)]);
        }
        cp_commit();
    }

    // stage norms into smem (coalesced; visible after first barrier)
    if (tid < 128){
        smem[OFF_NRM       + tid] = g_onorm[rowBase + tid];
        smem[OFF_NRM + 128 + tid] = g_onorm[colBase + tid];
        smem[OFF_NRM + 256 + tid] = g_fnorm[rowBase + tid];
        smem[OFF_NRM + 384 + tid] = g_fnorm[colBase + tid];
    }

    for (int c = 0; c < NCHUNK; c++){
        if (c < NCHUNK - 1) asm volatile("cp.async.wait_group 1;\n" ::: "memory");
        else                asm volatile("cp.async.wait_group 0;\n" ::: "memory");
        __syncthreads();                       // chunk c ready; stage sb2 fully drained

        const uint32_t baseA = smem_sh + (uint32_t)sb0 * 4u;
        const uint32_t baseB = baseA + 4096u * 4u;

        // refill chunk c+2 into sb2 (no warp can still be reading it)
        if (c + 2 < NCHUNK){
            float* base = smem + sb2;
            int kb = (c + 2) * KC;
            #pragma unroll
            for (int i = 0; i < 4; i++){
                int idx = tid + i * 256;
                int r = idx >> 3, g = idx & 7;
                int sw = r*32 + (((g ^ (r & 7)) << 2));
                cp16(base + sw,        &g_XcatH[(size_t)(rowBase + r)*DIN + kb + (g << 3)]);
                cp16(base + 4096 + sw, &g_XcatH[(size_t)(colBase + r)*DIN + kb + (g << 3)]);
            }
            cp_commit();
        }

        #pragma unroll
        for (int ks = 0; ks < 4; ks++){        // 4 k16-steps per 64-elem chunk
            const int g0 = 2*ks;
            uint32_t a[2][4];
            #pragma unroll
            for (int mi = 0; mi < 2; mi++){
                uint32_t ad = baseA + aRow[mi] + ((uint32_t)((g0 + aGh) ^ row8) << 4);
                ldsm4(a[mi][0], a[mi][1], a[mi][2], a[mi][3], ad);
            }
            uint32_t bfr[8][2];
            #pragma unroll
            for (int np = 0; np < 4; np++){
                uint32_t ad = baseB + bRow[np] + ((uint32_t)((g0 + bGh) ^ row8) << 4);
                ldsm4(bfr[2*np][0], bfr[2*np][1], bfr[2*np+1][0], bfr[2*np+1][1], ad);
            }
            #pragma unroll
            for (int mi = 0; mi < 2; mi++)
                #pragma unroll
                for (int ni = 0; ni < 8; ni++){
                    asm volatile(
                        "mma.sync.aligned.m16n8k16.row.col.f32.bf16.bf16.f32 "
                        "{%0,%1,%2,%3}, {%4,%5,%6,%7}, {%8,%9}, {%0,%1,%2,%3};\n"
                        : "+f"(acc[mi][ni][0]), "+f"(acc[mi][ni][1]),
                          "+f"(acc[mi][ni][2]), "+f"(acc[mi][ni][3])
                        : "r"(a[mi][0]), "r"(a[mi][1]), "r"(a[mi][2]), "r"(a[mi][3]),
                          "r"(bfr[ni][0]), "r"(bfr[ni][1]));
                }
        }

        int tmp = sb0; sb0 = sb1; sb1 = sb2; sb2 = tmp;   // rotate stages
    }
    __syncthreads();                           // all warps done with all stage buffers

    // Prefetch BOTH transposed Fea tiles into [0,16384) floats (overlaps Et epilogue).
    #pragma unroll
    for (int i = 0; i < 8; i++){
        int idx = tid + i * 256;
        int k = idx >> 5, gr = (idx & 31) << 2;
        cp16(smem + k*128 + gr,        &g_FeaT[(size_t)k*NROWS + rowBase + gr]);
        cp16(smem + 8192 + k*128 + gr, &g_FeaT[(size_t)k*NROWS + colBase + gr]);
    }
    cp_commit();

    const float ep    = g_par[0];
    const float invs  = g_par[1];
    const float invs0 = g_par[2];
    __half* Et16 = (__half*)(smem + OFF_ET16); // [128][LDEH] halves
    const float* on_r = smem + OFF_NRM;
    const float* on_c = smem + OFF_NRM + 128;
    const float* fn_r = smem + OFF_NRM + 256;
    const float* fn_c = smem + OFF_NRM + 384;

    {   // phase-1 epilogue: Do -> e_org, stage into Et16 (fragment -> (row,col))
        float rn[4], cn[16];
        #pragma unroll
        for (int mi = 0; mi < 2; mi++)
            #pragma unroll
            for (int rr = 0; rr < 2; rr++)
                rn[mi*2+rr] = on_r[rw + mi*16 + rr*8 + gid];
        #pragma unroll
        for (int ni = 0; ni < 8; ni++)
            #pragma unroll
            for (int cc = 0; cc < 2; cc++)
                cn[ni*2+cc] = on_c[cw + ni*8 + tig*2 + cc];
        #pragma unroll
        for (int mi = 0; mi < 2; mi++)
            #pragma unroll
            for (int ni = 0; ni < 8; ni++)
                #pragma unroll
                for (int rr = 0; rr < 2; rr++)
                    #pragma unroll
                    for (int cc = 0; cc < 2; cc++){
                        int lm = rw + mi*16 + rr*8 + gid;
                        int ln = cw + ni*8 + tig*2 + cc;
                        float d = fmaxf(rn[mi*2+rr] + cn[ni*2+cc]
                                        - 2.f * acc[mi][ni][rr*2+cc], 0.f);
                        Et16[lm*LDEH + ln] = __float2half(exp_neg(d * invs));
                    }
    }

    asm volatile("cp.async.wait_group 0;\n" ::: "memory");
    __syncthreads();                           // Fea tiles + Et16 visible

    // ---- phase 2: feature Gram, fp32 SIMT (RN accumulate — bias-free).
    //      k runs only over DOUT=50 real dims; k=50..63 are exact zeros
    //      (removing them is bit-identical: x + (+/-0) == x in RN) ----
    const float* FAt = smem;                   // [64][128], rows 50..63 unused
    const float* FBt = smem + 8192;
    const int tx = tid & 15, ty = tid >> 4;

    float fac[8][8];
    #pragma unroll
    for (int m = 0; m < 8; m++)
        #pragma unroll
        for (int n = 0; n < 8; n++) fac[m][n] = 0.f;

    #pragma unroll 10
    for (int k = 0; k < DOUT; k++){
        float4 a0 = *(const float4*)&FAt[k*128 + ty*8];
        float4 a1 = *(const float4*)&FAt[k*128 + ty*8 + 4];
        float4 b0 = *(const float4*)&FBt[k*128 + tx*8];
        float4 b1 = *(const float4*)&FBt[k*128 + tx*8 + 4];
        float a[8] = {a0.x, a0.y, a0.z, a0.w, a1.x, a1.y, a1.z, a1.w};
        float b[8] = {b0.x, b0.y, b0.z, b0.w, b1.x, b1.y, b1.z, b1.w};
        #pragma unroll
        for (int m = 0; m < 8; m++)
            #pragma unroll
            for (int n = 0; n < 8; n++) fac[m][n] += a[m] * b[n];
    }

    // ---- final epilogue: per-TILE classification; Et16 read as packed half2 ----
    const bool diagTile = (bi == bj);
    const bool sdTile   = (bj - bi == 32);     // ci - ri == NHALF  <=>  ln == lm
    const int  cls      = (bj < 32) ? 0 : ((bi >= 32) ? 1 : 2);
    const float mult    = diagTile ? 1.f : 2.f;

    float fnr[8], fnc[8];
    #pragma unroll
    for (int m = 0; m < 8; m++) fnr[m] = fn_r[ty*8 + m];
    #pragma unroll
    for (int n = 0; n < 8; n++) fnc[n] = fn_c[tx*8 + n];

    float s = 0.f, sd = 0.f;
    #pragma unroll
    for (int m = 0; m < 8; m++){
        const int lm = ty*8 + m;
        float eor[8];
        #pragma unroll
        for (int j = 0; j < 4; j++){
            __half2 h2 = *(const __half2*)&Et16[lm*LDEH + tx*8 + 2*j];
            float2 f2 = __half22float2(h2);
            eor[2*j]   = f2.x;
            eor[2*j+1] = f2.y;
        }
        float kvrow[8];
        #pragma unroll
        for (int n = 0; n < 8; n++){
            float dd = fmaxf(fnr[m] + fnc[n] - 2.f * fac[m][n], 0.f);
            float eo = eor[n];
            kvrow[n] = (1.f - ep) * exp_neg(dd * invs0) * eo + ep * eo;
        }
        // diagonal exclusion / sd extraction hoisted out of the n-loop:
        const int nd = lm - tx*8;              // n index where ln == lm (if 0..7)
        if (diagTile && (unsigned)nd < 8u) kvrow[nd] = 0.f;
        if (sdTile   && (unsigned)nd < 8u) sd += kvrow[nd];
        #pragma unroll
        for (int n = 0; n < 8; n++) s += kvrow[n];
    }
    s *= mult;                                  // sd counted once per pair

    #pragma unroll
    for (int off = 16; off; off >>= 1)
        s += __shfl_xor_sync(0xffffffffu, s, off);
    if (sdTile){
        #pragma unroll
        for (int off = 16; off; off >>= 1)
            sd += __shfl_xor_sync(0xffffffffu, sd, off);
    }
    if (lane == 0){
        atomicAdd(&g_acc[cls], (double)s);
        if (sdTile) atomicAdd(&g_acc[3], (double)sd);
    }

    // ---- folded finalize: last block to finish computes mmd2 ----
    __syncthreads();                            // all this block's atomics issued
    if (tid == 0){
        __threadfence();                        // publish g_acc updates
        unsigned int old = atomicAdd(&g_done, 1u);
        if (old == NPAIR - 1u){                 // last block: all others fenced+counted
            double n = (double)NHALF;
            double denom = n * (n - 1.0);
            double xx = g_acc[0] / denom;
            double yy = g_acc[1] / denom;
            double xy = (0.5 * g_acc[2] - g_acc[3]) / denom;
            out[0] = (float)(xx - 2.0 * xy + yy);
        }
    }
}

// ---------------- launch ----------------
extern "C" void kernel_launch(void* const* d_in, const int* in_sizes, int n_in,
                              void* d_out, int out_size){
    const float* Xs  = (const float*)d_in[0];
    const float* Xt  = (const float*)d_in[1];
    const float* W1  = (const float*)d_in[2];
    const float* b1  = (const float*)d_in[3];
    const float* W2  = (const float*)d_in[4];
    const float* b2  = (const float*)d_in[5];
    const float* W3  = (const float*)d_in[6];
    const float* b3  = (const float*)d_in[7];
    const float* W4  = (const float*)d_in[8];
    const float* b4  = (const float*)d_in[9];
    const float* eps = (const float*)d_in[10];
    const float* sg  = (const float*)d_in[11];
    const float* sg0 = (const float*)d_in[12];

    feat_kernel<<<NROWS/32, 256>>>(Xs, Xt, W1, b1, W2, b2, W3, b3, W4, b4,
                                   eps, sg, sg0);

    cudaFuncSetAttribute(pair_kernel, cudaFuncAttributeMaxDynamicSharedMemorySize, SMEM_BYTES);
    pair_kernel<<<NPAIR, 256, SMEM_BYTES>>>((float*)d_out);
}